// round 3
// baseline (speedup 1.0000x reference)
#include <cuda_runtime.h>
#include <math.h>
#include <float.h>

#define L_SEQ 2048
#define NB 2
#define DM 1024
#define NH 16
#define DHEAD 64
#define SPAN_W 128
#define MROWS (L_SEQ * NB)          // 4096
#define HB (NH * NB)                // 32

typedef unsigned long long u64t;

// ---------------- packed f32x2 helpers (sm_103a FFMA2) ----------------
__device__ __forceinline__ void fma2(u64t& d, u64t a, u64t b) {
    asm("fma.rn.f32x2 %0, %1, %2, %0;" : "+l"(d) : "l"(a), "l"(b));
}
__device__ __forceinline__ u64t pack2(float x, float y) {
    u64t r; asm("mov.b64 %0, {%1, %2};" : "=l"(r) : "f"(x), "f"(y)); return r;
}
__device__ __forceinline__ float2 unpack2(u64t v) {
    float2 r; asm("mov.b64 {%0, %1}, %2;" : "=f"(r.x), "=f"(r.y) : "l"(v)); return r;
}

// ---------------- static scratch (no allocations allowed) ----------------
__device__ float g_q[HB * L_SEQ * DHEAD];        // [h*B+b][l][dk]
__device__ float g_k[HB * L_SEQ * DHEAD];
__device__ float g_v[HB * L_SEQ * DHEAD];
__device__ float g_attnout[MROWS * DM];          // [l*B+b][h*dv]
__device__ float g_fc[MROWS * DM];               // FC output (pre-LN)
__device__ float g_rowm[HB * L_SEQ];             // softmax row max
__device__ float g_rowl[HB * L_SEQ];             // softmax row sum

// =========================================================================
// Double-buffered SGEMM core, FFMA2 inner loop.
// BM=BN=128, BK=8, 256 thr, 8x8/thr.  A duplicated in smem for broadcast
// pairs; B pairs free via LDS.128.
// =========================================================================
__device__ __forceinline__ void gemm_tile(
    const float* __restrict__ A, const float* __restrict__ W,
    const float* __restrict__ bias, float* __restrict__ out,
    int K, int N, int m0, int n0, int transhead)
{
    __shared__ float As[2][8][256];   // duplicated: [k][2m], [k][2m+1] both = A
    __shared__ float Bs[2][8][128];

    const int tid = threadIdx.x;
    const int tx = tid & 15, ty = tid >> 4;

    u64t acc2[8][4];
#pragma unroll
    for (int r = 0; r < 8; r++)
#pragma unroll
        for (int c = 0; c < 4; c++) acc2[r][c] = 0ull;

    const int a_m  = tid >> 1;
    const int a_kq = (tid & 1) << 2;
    const int b_k  = tid >> 5;
    const int b_n  = (tid & 31) << 2;

    const float* Aptr = A + (size_t)(m0 + a_m) * K + a_kq;
    const float* Wptr = W + (size_t)b_k * N + n0 + b_n;

    float4 av = *(const float4*)(Aptr);
    float4 bv = *(const float4*)(Wptr);

    int buf = 0;
    As[0][a_kq + 0][2 * a_m] = av.x;  As[0][a_kq + 0][2 * a_m + 1] = av.x;
    As[0][a_kq + 1][2 * a_m] = av.y;  As[0][a_kq + 1][2 * a_m + 1] = av.y;
    As[0][a_kq + 2][2 * a_m] = av.z;  As[0][a_kq + 2][2 * a_m + 1] = av.z;
    As[0][a_kq + 3][2 * a_m] = av.w;  As[0][a_kq + 3][2 * a_m + 1] = av.w;
    *(float4*)&Bs[0][b_k][b_n] = bv;
    __syncthreads();

    for (int k0 = 0; k0 < K; k0 += 8) {
        const int has_next = (k0 + 8 < K);
        if (has_next) {
            av = *(const float4*)(Aptr + k0 + 8);
            bv = *(const float4*)(Wptr + (size_t)(k0 + 8) * N);
        }
#pragma unroll
        for (int kk = 0; kk < 8; kk++) {
            u64t a2[8], b2[4];
            {
                const ulonglong2* bp = (const ulonglong2*)&Bs[buf][kk][tx * 8];
                ulonglong2 t0 = bp[0], t1 = bp[1];
                b2[0] = t0.x; b2[1] = t0.y; b2[2] = t1.x; b2[3] = t1.y;
            }
#pragma unroll
            for (int r = 0; r < 8; r++)
                a2[r] = *(const u64t*)&As[buf][kk][(ty * 8 + r) * 2];
#pragma unroll
            for (int r = 0; r < 8; r++)
#pragma unroll
                for (int c = 0; c < 4; c++)
                    fma2(acc2[r][c], a2[r], b2[c]);
        }
        if (has_next) {
            const int nb = buf ^ 1;
            As[nb][a_kq + 0][2 * a_m] = av.x;  As[nb][a_kq + 0][2 * a_m + 1] = av.x;
            As[nb][a_kq + 1][2 * a_m] = av.y;  As[nb][a_kq + 1][2 * a_m + 1] = av.y;
            As[nb][a_kq + 2][2 * a_m] = av.z;  As[nb][a_kq + 2][2 * a_m + 1] = av.z;
            As[nb][a_kq + 3][2 * a_m] = av.w;  As[nb][a_kq + 3][2 * a_m + 1] = av.w;
            *(float4*)&Bs[nb][b_k][b_n] = bv;
            __syncthreads();
            buf = nb;
        }
    }

    const int n_base = n0 + tx * 8;
    float bvals[8];
#pragma unroll
    for (int c = 0; c < 8; c++) bvals[c] = bias[n_base + c];

    float accf[8][8];
#pragma unroll
    for (int r = 0; r < 8; r++)
#pragma unroll
        for (int c = 0; c < 4; c++) {
            float2 f = unpack2(acc2[r][c]);
            accf[r][2 * c] = f.x; accf[r][2 * c + 1] = f.y;
        }

    if (!transhead) {
#pragma unroll
        for (int r = 0; r < 8; r++) {
            int m = m0 + ty * 8 + r;
            float* dst = out + (size_t)m * N + n_base;
            *(float4*)&dst[0] = make_float4(accf[r][0] + bvals[0], accf[r][1] + bvals[1],
                                            accf[r][2] + bvals[2], accf[r][3] + bvals[3]);
            *(float4*)&dst[4] = make_float4(accf[r][4] + bvals[4], accf[r][5] + bvals[5],
                                            accf[r][6] + bvals[6], accf[r][7] + bvals[7]);
        }
    } else {
        const int h = n_base >> 6;
        const int dkb = n_base & 63;
#pragma unroll
        for (int r = 0; r < 8; r++) {
            int m = m0 + ty * 8 + r;
            int l = m >> 1, bb = m & 1;
            float* dst = out + ((size_t)(h * NB + bb) * L_SEQ + l) * DHEAD + dkb;
            *(float4*)&dst[0] = make_float4(accf[r][0] + bvals[0], accf[r][1] + bvals[1],
                                            accf[r][2] + bvals[2], accf[r][3] + bvals[3]);
            *(float4*)&dst[4] = make_float4(accf[r][4] + bvals[4], accf[r][5] + bvals[5],
                                            accf[r][6] + bvals[6], accf[r][7] + bvals[7]);
        }
    }
}

__global__ void __launch_bounds__(256, 2)
sgemm_qkv_kernel(const float* __restrict__ q, const float* __restrict__ k,
                 const float* __restrict__ v,
                 const float* __restrict__ Wq, const float* __restrict__ Wk,
                 const float* __restrict__ Wv,
                 const float* __restrict__ bq, const float* __restrict__ bk,
                 const float* __restrict__ bv)
{
    const int z = blockIdx.z;
    const float* A = (z == 0) ? q : (z == 1) ? k : v;
    const float* W = (z == 0) ? Wq : (z == 1) ? Wk : Wv;
    const float* bias = (z == 0) ? bq : (z == 1) ? bk : bv;
    float* out = (z == 0) ? g_q : (z == 1) ? g_k : g_v;
    gemm_tile(A, W, bias, out, DM, NH * DHEAD,
              blockIdx.x * 128, blockIdx.y * 128, 1);
}

__global__ void __launch_bounds__(256, 2)
sgemm_fc_kernel(const float* __restrict__ Wfc, const float* __restrict__ bfc)
{
    gemm_tile(g_attnout, Wfc, bfc, g_fc, DM, DM,
              blockIdx.x * 128, blockIdx.y * 128, 0);
}

// =========================================================================
// Banded attention with FFMA2.
// Phase 1: scores via c-packed FFMA2 (K transposed, B-pairs free).
// Phase 2: P@V via j-reduction-packed FFMA2 (V transposed -> j pairs free).
// =========================================================================
#define QS_STRIDE 132
#define VT_STRIDE 130
#define PH_STRIDE 66
#define QS_FLOATS (64 * QS_STRIDE)            // 8448
#define KV_FLOATS 8704                         // >= 64*132, >= 64*130
#define PS_FLOATS (128 * PH_STRIDE)           // 8448
#define ATTN_SMEM_BYTES ((QS_FLOATS + KV_FLOATS + PS_FLOATS) * 4)

__global__ void __launch_bounds__(256, 2)
attn_kernel(float* __restrict__ attn_raw)
{
    extern __shared__ float smx[];
    float* Qs  = smx;                       // [dk][i] transposed, stride 132
    float* KVs = smx + QS_FLOATS;           // K: [dk][j] / V: [dv][j] stride 130
    float* Ps  = smx + QS_FLOATS + KV_FLOATS;  // [row][j-half] stride 66

    const int tid = threadIdx.x;
    const int tx = tid & 15, ty = tid >> 4;
    const int i0 = blockIdx.x * 128;
    const int hb = blockIdx.y;

    const float* Qg = g_q + (size_t)hb * L_SEQ * DHEAD;
    const float* Kg = g_k + (size_t)hb * L_SEQ * DHEAD;
    const float* Vg = g_v + (size_t)hb * L_SEQ * DHEAD;
    float* rawbase = attn_raw + (size_t)hb * L_SEQ * L_SEQ;

    // load Q tile transposed: Qs[dk][i]
    {
        const float* src = Qg + (size_t)i0 * DHEAD;
        for (int idx = tid; idx < 128 * 16; idx += 256) {
            int r = idx >> 4, kq = (idx & 15) << 2;
            float4 v = *(const float4*)&src[r * 64 + kq];
            Qs[(kq + 0) * QS_STRIDE + r] = v.x;
            Qs[(kq + 1) * QS_STRIDE + r] = v.y;
            Qs[(kq + 2) * QS_STRIDE + r] = v.z;
            Qs[(kq + 3) * QS_STRIDE + r] = v.w;
        }
    }

    float rm[8];
#pragma unroll
    for (int r = 0; r < 8; r++) rm[r] = -FLT_MAX;

    const int ibase = i0 + ty * 8;

    // ---------------- Phase 1: raw scores + row max ----------------
    for (int cch = 0; cch < 3; cch++) {
        int j0 = i0 + (cch - 1) * 128;
        if (j0 < 0 || j0 >= L_SEQ) continue;
        __syncthreads();
        {
            const float* src = Kg + (size_t)j0 * DHEAD;
            for (int idx = tid; idx < 128 * 16; idx += 256) {
                int r = idx >> 4, kq = (idx & 15) << 2;
                float4 v = *(const float4*)&src[r * 64 + kq];
                KVs[(kq + 0) * QS_STRIDE + r] = v.x;
                KVs[(kq + 1) * QS_STRIDE + r] = v.y;
                KVs[(kq + 2) * QS_STRIDE + r] = v.z;
                KVs[(kq + 3) * QS_STRIDE + r] = v.w;
            }
        }
        __syncthreads();
        u64t s2[8][4];
#pragma unroll
        for (int r = 0; r < 8; r++)
#pragma unroll
            for (int c = 0; c < 4; c++) s2[r][c] = 0ull;

        for (int kk = 0; kk < 64; kk++) {
            float a[8];
            *(float4*)&a[0] = *(const float4*)&Qs[kk * QS_STRIDE + ty * 8];
            *(float4*)&a[4] = *(const float4*)&Qs[kk * QS_STRIDE + ty * 8 + 4];
            u64t b2[4];
            {
                const ulonglong2* bp = (const ulonglong2*)&KVs[kk * QS_STRIDE + tx * 8];
                ulonglong2 t0 = bp[0], t1 = bp[1];
                b2[0] = t0.x; b2[1] = t0.y; b2[2] = t1.x; b2[3] = t1.y;
            }
#pragma unroll
            for (int r = 0; r < 8; r++) {
                u64t a2 = pack2(a[r], a[r]);
#pragma unroll
                for (int c = 0; c < 4; c++)
                    fma2(s2[r][c], a2, b2[c]);
            }
        }

        float s[8][8];
#pragma unroll
        for (int r = 0; r < 8; r++)
#pragma unroll
            for (int c = 0; c < 4; c++) {
                float2 f = unpack2(s2[r][c]);
                s[r][2 * c] = f.x; s[r][2 * c + 1] = f.y;
            }

        const int jbase = j0 + tx * 8;
#pragma unroll
        for (int r = 0; r < 8; r++) {
            int i = ibase + r;
            float* rowp = rawbase + (size_t)i * L_SEQ;
#pragma unroll
            for (int c2 = 0; c2 < 8; c2++) {
                int j = jbase + c2;
                int d = i - j;
                if (d >= -SPAN_W && d <= SPAN_W) {
                    float v = s[r][c2] * 0.125f;
                    rowp[j] = v;
                    rm[r] = fmaxf(rm[r], v);
                }
            }
        }
    }

    // reduce row max across the 16 tx lanes
#pragma unroll
    for (int r = 0; r < 8; r++) {
#pragma unroll
        for (int off = 8; off > 0; off >>= 1)
            rm[r] = fmaxf(rm[r], __shfl_xor_sync(0xffffffffu, rm[r], off, 16));
    }

    // ---------------- Phase 2: P = exp(s-m), O = P @ V, row sums ---------
    u64t O2[8][4];
    float ll[8];
#pragma unroll
    for (int r = 0; r < 8; r++) {
        ll[r] = 0.f;
#pragma unroll
        for (int c = 0; c < 4; c++) O2[r][c] = 0ull;
    }

    for (int cch = 0; cch < 3; cch++) {
        int j0 = i0 + (cch - 1) * 128;
        if (j0 < 0 || j0 >= L_SEQ) continue;
        __syncthreads();   // prev chunk's KVs/Ps fully consumed
        {
            // load V transposed: Vt[dv][j], stride 130
            const float* src = Vg + (size_t)j0 * DHEAD;
            for (int idx = tid; idx < 128 * 16; idx += 256) {
                int r = idx >> 4, kq = (idx & 15) << 2;
                float4 v = *(const float4*)&src[r * 64 + kq];
                KVs[(kq + 0) * VT_STRIDE + r] = v.x;
                KVs[(kq + 1) * VT_STRIDE + r] = v.y;
                KVs[(kq + 2) * VT_STRIDE + r] = v.z;
                KVs[(kq + 3) * VT_STRIDE + r] = v.w;
            }
        }
        __syncthreads();   // V ready

#pragma unroll
        for (int half = 0; half < 2; half++) {
            if ((tx >> 3) == half) {
                const int txh = tx & 7;
                const int jbase = j0 + tx * 8;
#pragma unroll
                for (int r = 0; r < 8; r++) {
                    int i = ibase + r;
                    const float* rowp = rawbase + (size_t)i * L_SEQ;
                    float* prow = Ps + (size_t)(ty * 8 + r) * PH_STRIDE + txh * 8;
#pragma unroll
                    for (int c2 = 0; c2 < 8; c2++) {
                        int j = jbase + c2;
                        int d = i - j;
                        float p = 0.f;
                        if (d >= -SPAN_W && d <= SPAN_W)
                            p = __expf(rowp[j] - rm[r]);
                        ll[r] += p;
                        prow[c2] = p;
                    }
                }
            }
            __syncthreads();   // Ps half ready
            const int joff = half * 64;
            for (int jj = 0; jj < 64; jj += 2) {
                u64t pv2[8], v2[4];
#pragma unroll
                for (int r = 0; r < 8; r++)
                    pv2[r] = *(const u64t*)&Ps[(ty * 8 + r) * PH_STRIDE + jj];
#pragma unroll
                for (int c = 0; c < 4; c++)
                    v2[c] = *(const u64t*)&KVs[(tx * 4 + c) * VT_STRIDE + jj + joff];
#pragma unroll
                for (int r = 0; r < 8; r++)
#pragma unroll
                    for (int c = 0; c < 4; c++)
                        fma2(O2[r][c], pv2[r], v2[c]);
            }
            if (half == 0) __syncthreads();   // half consumed before overwrite
        }
    }

    // reduce row sums across tx lanes
#pragma unroll
    for (int r = 0; r < 8; r++) {
#pragma unroll
        for (int off = 8; off > 0; off >>= 1)
            ll[r] += __shfl_xor_sync(0xffffffffu, ll[r], off, 16);
    }

    const int h = hb >> 1, bb = hb & 1;
#pragma unroll
    for (int r = 0; r < 8; r++) {
        int i = ibase + r;
        float inv = 1.f / ll[r];
        float2 o01 = unpack2(O2[r][0]);
        float2 o23 = unpack2(O2[r][1]);
        float2 o45 = unpack2(O2[r][2]);
        float2 o67 = unpack2(O2[r][3]);
        float4 o4 = make_float4((o01.x + o01.y) * inv, (o23.x + o23.y) * inv,
                                (o45.x + o45.y) * inv, (o67.x + o67.y) * inv);
        *(float4*)&g_attnout[((size_t)i * NB + bb) * DM + h * DHEAD + tx * 4] = o4;
        if (tx == 0) {
            g_rowm[hb * L_SEQ + i] = rm[r];
            g_rowl[hb * L_SEQ + i] = ll[r];
        }
    }
}

// =========================================================================
// Normalize raw scores -> softmax weights; zero out-of-band.
// =========================================================================
__global__ void __launch_bounds__(256)
attn_norm_kernel(float* __restrict__ attn)
{
    const int row = blockIdx.x;               // hb*L + i
    const int i = row & (L_SEQ - 1);
    const float m = g_rowm[row];
    const float inv = 1.f / g_rowl[row];
    float* p = attn + (size_t)row * L_SEQ;
    const int j0 = threadIdx.x * 8;
    float out[8];
#pragma unroll
    for (int u = 0; u < 8; u++) {
        int j = j0 + u;
        int d = i - j;
        float raw = 0.f;
        bool inband = (d >= -SPAN_W && d <= SPAN_W);
        if (inband) raw = p[j];
        out[u] = inband ? __expf(raw - m) * inv : 0.f;
    }
    *(float4*)&p[j0]     = make_float4(out[0], out[1], out[2], out[3]);
    *(float4*)&p[j0 + 4] = make_float4(out[4], out[5], out[6], out[7]);
}

// =========================================================================
// Residual + LayerNorm.
// =========================================================================
__global__ void __launch_bounds__(256)
ln_kernel(const float* __restrict__ query, const float* __restrict__ gamma,
          const float* __restrict__ beta, float* __restrict__ y)
{
    __shared__ float red[16];
    const int row = blockIdx.x;
    const int t = threadIdx.x;

    float4 f = *(const float4*)&g_fc[(size_t)row * DM + t * 4];
    float4 q = *(const float4*)&query[(size_t)row * DM + t * 4];
    float v0 = f.x + q.x, v1 = f.y + q.y, v2 = f.z + q.z, v3 = f.w + q.w;

    float s = v0 + v1 + v2 + v3;
    float s2 = v0 * v0 + v1 * v1 + v2 * v2 + v3 * v3;
#pragma unroll
    for (int off = 16; off > 0; off >>= 1) {
        s  += __shfl_xor_sync(0xffffffffu, s, off);
        s2 += __shfl_xor_sync(0xffffffffu, s2, off);
    }
    const int warp = t >> 5, lane = t & 31;
    if (lane == 0) { red[warp] = s; red[warp + 8] = s2; }
    __syncthreads();
    if (t < 32) {
        float a  = (lane < 8) ? red[lane] : 0.f;
        float b2 = (lane < 8) ? red[lane + 8] : 0.f;
#pragma unroll
        for (int off = 4; off > 0; off >>= 1) {
            a  += __shfl_xor_sync(0xffffffffu, a, off);
            b2 += __shfl_xor_sync(0xffffffffu, b2, off);
        }
        if (lane == 0) { red[0] = a; red[1] = b2; }
    }
    __syncthreads();
    const float mean = red[0] * (1.f / DM);
    const float var  = red[1] * (1.f / DM) - mean * mean;
    const float rstd = rsqrtf(var + 1e-5f);

    float4 g  = *(const float4*)&gamma[t * 4];
    float4 be = *(const float4*)&beta[t * 4];
    float4 o;
    o.x = (v0 - mean) * rstd * g.x + be.x;
    o.y = (v1 - mean) * rstd * g.y + be.y;
    o.z = (v2 - mean) * rstd * g.z + be.z;
    o.w = (v3 - mean) * rstd * g.w + be.w;
    *(float4*)&y[(size_t)row * DM + t * 4] = o;
}

// =========================================================================
extern "C" void kernel_launch(void* const* d_in, const int* in_sizes, int n_in,
                              void* d_out, int out_size)
{
    const float* query = (const float*)d_in[0];
    const float* key   = (const float*)d_in[1];
    const float* value = (const float*)d_in[2];
    const float* Wq    = (const float*)d_in[3];
    const float* bq    = (const float*)d_in[4];
    const float* Wk    = (const float*)d_in[5];
    const float* bk    = (const float*)d_in[6];
    const float* Wv    = (const float*)d_in[7];
    const float* bv    = (const float*)d_in[8];
    const float* Wfc   = (const float*)d_in[9];
    const float* bfc   = (const float*)d_in[10];
    const float* gamma = (const float*)d_in[11];
    const float* beta  = (const float*)d_in[12];

    float* y_out = (float*)d_out;
    float* attn_out = y_out + (size_t)L_SEQ * NB * DM;

    cudaFuncSetAttribute(attn_kernel,
                         cudaFuncAttributeMaxDynamicSharedMemorySize,
                         ATTN_SMEM_BYTES);

    dim3 gqkv(MROWS / 128, DM / 128, 3);
    sgemm_qkv_kernel<<<gqkv, 256>>>(query, key, value, Wq, Wk, Wv, bq, bk, bv);

    attn_kernel<<<dim3(L_SEQ / 128, HB), 256, ATTN_SMEM_BYTES>>>(attn_out);

    sgemm_fc_kernel<<<dim3(MROWS / 128, DM / 128), 256>>>(Wfc, bfc);

    ln_kernel<<<MROWS, 256>>>(query, gamma, beta, y_out);

    attn_norm_kernel<<<HB * L_SEQ, 256>>>(attn_out);
}

// round 5
// speedup vs baseline: 1.8993x; 1.8993x over previous
#include <cuda_runtime.h>
#include <cuda_bf16.h>
#include <math.h>
#include <float.h>
#include <stdint.h>

#define L_SEQ 2048
#define NB 2
#define DM 1024
#define NH 16
#define DHEAD 64
#define SPAN_W 128
#define MROWS (L_SEQ * NB)          // 4096
#define HB (NH * NB)                // 32

// ---------------- static scratch (no allocations allowed) ----------------
__device__ float g_q[HB * L_SEQ * DHEAD];        // [h*B+b][l][dk]
__device__ float g_k[HB * L_SEQ * DHEAD];
__device__ float g_v[HB * L_SEQ * DHEAD];
__device__ float g_fc[MROWS * DM];               // FC output (pre-LN)
__device__ float g_rowm[HB * L_SEQ];             // softmax row max
__device__ float g_rowl[HB * L_SEQ];             // softmax row sum

// bf16 split operands for tensor-core GEMMs
__device__ __nv_bfloat16 g_inhi[3][MROWS * DM];  // q/k/v inputs, hi part
__device__ __nv_bfloat16 g_inlo[3][MROWS * DM];  // lo part
__device__ __nv_bfloat16 g_wthi[4][DM * DM];     // W^T [n][k] hi (Wq,Wk,Wv,Wfc)
__device__ __nv_bfloat16 g_wtlo[4][DM * DM];     // W^T lo
__device__ __nv_bfloat16 g_aohi[MROWS * DM];     // attnout hi (written by attn)
__device__ __nv_bfloat16 g_aolo[MROWS * DM];     // attnout lo

// ---------------- warp MMA helpers (legacy path, sm_80+ ISA) -------------
__device__ __forceinline__ uint32_t smem_u32(const void* p) {
    uint32_t a;
    asm("{ .reg .u64 t; cvta.to.shared.u64 t, %1; cvt.u32.u64 %0, t; }"
        : "=r"(a) : "l"(p));
    return a;
}
__device__ __forceinline__ void ldsm4(uint32_t (&r)[4], uint32_t addr) {
    asm volatile("ldmatrix.sync.aligned.m8n8.x4.shared.b16 {%0,%1,%2,%3}, [%4];"
                 : "=r"(r[0]), "=r"(r[1]), "=r"(r[2]), "=r"(r[3]) : "r"(addr));
}
__device__ __forceinline__ void mma_bf16(float (&d)[4], const uint32_t (&a)[4],
                                         uint32_t b0, uint32_t b1) {
    asm volatile(
        "mma.sync.aligned.m16n8k16.row.col.f32.bf16.bf16.f32 "
        "{%0,%1,%2,%3}, {%4,%5,%6,%7}, {%8,%9}, {%0,%1,%2,%3};"
        : "+f"(d[0]), "+f"(d[1]), "+f"(d[2]), "+f"(d[3])
        : "r"(a[0]), "r"(a[1]), "r"(a[2]), "r"(a[3]), "r"(b0), "r"(b1));
}

// ======================== converter kernels ==============================
__global__ void __launch_bounds__(256)
conv_in_kernel(const float* __restrict__ q, const float* __restrict__ k,
               const float* __restrict__ v)
{
    const int z = blockIdx.y;
    const float* src = (z == 0) ? q : (z == 1) ? k : v;
    __nv_bfloat16* dhi = g_inhi[z];
    __nv_bfloat16* dlo = g_inlo[z];
    size_t base = ((size_t)blockIdx.x * 256 + threadIdx.x) * 8;
    float4 a = *(const float4*)(src + base);
    float4 b = *(const float4*)(src + base + 4);
    __nv_bfloat16 hi[8], lo[8];
    float xs[8] = {a.x, a.y, a.z, a.w, b.x, b.y, b.z, b.w};
#pragma unroll
    for (int i = 0; i < 8; i++) {
        hi[i] = __float2bfloat16(xs[i]);
        lo[i] = __float2bfloat16(xs[i] - __bfloat162float(hi[i]));
    }
    *(uint4*)(dhi + base) = *(uint4*)hi;
    *(uint4*)(dlo + base) = *(uint4*)lo;
}

// weights: W[k][n] fp32 -> Wt_hi/lo[n][k] bf16 (transpose via smem)
__global__ void __launch_bounds__(256)
conv_w_kernel(const float* __restrict__ Wq, const float* __restrict__ Wk,
              const float* __restrict__ Wv, const float* __restrict__ Wfc)
{
    __shared__ float tile[32][33];
    const int z = blockIdx.z;
    const float* W = (z == 0) ? Wq : (z == 1) ? Wk : (z == 2) ? Wv : Wfc;
    __nv_bfloat16* dhi = g_wthi[z];
    __nv_bfloat16* dlo = g_wtlo[z];
    const int n0 = blockIdx.x * 32, k0 = blockIdx.y * 32;
    const int c = threadIdx.x & 31, r0 = (threadIdx.x >> 5) * 4;
#pragma unroll
    for (int rr = 0; rr < 4; rr++)
        tile[r0 + rr][c] = W[(size_t)(k0 + r0 + rr) * DM + n0 + c];
    __syncthreads();
#pragma unroll
    for (int rr = 0; rr < 4; rr++) {
        int n = n0 + r0 + rr;
        float x = tile[c][r0 + rr];
        __nv_bfloat16 hi = __float2bfloat16(x);
        __nv_bfloat16 lo = __float2bfloat16(x - __bfloat162float(hi));
        dhi[(size_t)n * DM + k0 + c] = hi;
        dlo[(size_t)n * DM + k0 + c] = lo;
    }
}

// ======================== split-bf16 HMMA GEMM ===========================
// C(4096x1024) = A @ W + bias via D = Ah*Bh + Ah*Bl + Al*Bh.
// BM=BN=128, BK=32, 8 warps (warp tile 32x64), double-buffered smem.
// Tile smem layout: rows of 32 bf16 padded to 40 (80B) -> conflict-free LDSM.
#define TS 40                          // row stride in bf16
#define TILE_B (128 * TS * 2)          // 10240 bytes per tile
#define GEMM_SMEM_BYTES (2 * 4 * TILE_B)   // 81920

__global__ void __launch_bounds__(256, 1)
mma_gemm_kernel(const float* __restrict__ bq, const float* __restrict__ bk,
                const float* __restrict__ bv, const float* __restrict__ bfc,
                int is_fc)
{
    extern __shared__ char dyn[];
    const uint32_t sb = smem_u32(dyn);
    const int tid = threadIdx.x, wid = tid >> 5, lane = tid & 31;
    const int m0 = blockIdx.x * 128, n0 = blockIdx.y * 128;
    const int z = blockIdx.z;

    const __nv_bfloat16 *Ah, *Al, *Bh, *Bl;
    const float* bias;
    if (is_fc) {
        Ah = g_aohi; Al = g_aolo; Bh = g_wthi[3]; Bl = g_wtlo[3]; bias = bfc;
    } else {
        Ah = g_inhi[z]; Al = g_inlo[z]; Bh = g_wthi[z]; Bl = g_wtlo[z];
        bias = (z == 0) ? bq : (z == 1) ? bk : bv;
    }
    const __nv_bfloat16* srcs[4] = {
        Ah + (size_t)m0 * DM, Al + (size_t)m0 * DM,
        Bh + (size_t)n0 * DM, Bl + (size_t)n0 * DM };

    const int wm = (wid & 3) * 32;          // warp M offset
    const int wn = (wid >> 2) * 64;         // warp N offset

    float acc[2][8][4];
#pragma unroll
    for (int ms = 0; ms < 2; ms++)
#pragma unroll
        for (int ns = 0; ns < 8; ns++)
#pragma unroll
            for (int c = 0; c < 4; c++) acc[ms][ns][c] = 0.f;

    const int r_ld  = tid >> 2;             // chunk row (0..63), +64 for u=1
    const int c_ld  = (tid & 3) * 8;        // bf16 col within BK

    uint4 stage[4][2];
#pragma unroll
    for (int t = 0; t < 4; t++) {
#pragma unroll
        for (int u = 0; u < 2; u++)
            stage[t][u] = *(const uint4*)(srcs[t] + (size_t)(r_ld + u * 64) * DM + c_ld);
    }
#pragma unroll
    for (int t = 0; t < 4; t++)
#pragma unroll
        for (int u = 0; u < 2; u++)
            *(uint4*)(dyn + t * TILE_B + ((r_ld + u * 64) * TS + c_ld) * 2) = stage[t][u];
    __syncthreads();

    // LDSM lane addressing (within a tile, in bf16 units)
    const int rowA = wm + (lane & 15);
    const int colA = (lane >> 4) << 3;
    const int rowB = wn + (lane & 7) + ((lane >> 4) << 3);
    const int colB = ((lane >> 3) & 1) << 3;

    for (int step = 0; step < 32; step++) {
        const int buf = step & 1;
        const uint32_t base = sb + buf * (4 * TILE_B);
        const int has_next = (step + 1 < 32);
        if (has_next) {
            const int k0 = (step + 1) * 32;
#pragma unroll
            for (int t = 0; t < 4; t++)
#pragma unroll
                for (int u = 0; u < 2; u++)
                    stage[t][u] = *(const uint4*)(srcs[t] + (size_t)(r_ld + u * 64) * DM + k0 + c_ld);
        }

#pragma unroll
        for (int kh = 0; kh < 32; kh += 16) {
            uint32_t ah[2][4], al[2][4];
#pragma unroll
            for (int ms = 0; ms < 2; ms++) {
                uint32_t off = ((rowA + ms * 16) * TS + kh + colA) * 2;
                ldsm4(ah[ms], base + 0 * TILE_B + off);
                ldsm4(al[ms], base + 1 * TILE_B + off);
            }
            uint32_t bh[8][2], bl[8][2];
#pragma unroll
            for (int np = 0; np < 4; np++) {
                uint32_t off = ((rowB + np * 16) * TS + kh + colB) * 2;
                uint32_t t4[4];
                ldsm4(t4, base + 2 * TILE_B + off);
                bh[2 * np][0] = t4[0]; bh[2 * np][1] = t4[1];
                bh[2 * np + 1][0] = t4[2]; bh[2 * np + 1][1] = t4[3];
                ldsm4(t4, base + 3 * TILE_B + off);
                bl[2 * np][0] = t4[0]; bl[2 * np][1] = t4[1];
                bl[2 * np + 1][0] = t4[2]; bl[2 * np + 1][1] = t4[3];
            }
#pragma unroll
            for (int ms = 0; ms < 2; ms++)
#pragma unroll
                for (int ns = 0; ns < 8; ns++) {
                    mma_bf16(acc[ms][ns], ah[ms], bh[ns][0], bh[ns][1]);
                    mma_bf16(acc[ms][ns], ah[ms], bl[ns][0], bl[ns][1]);
                    mma_bf16(acc[ms][ns], al[ms], bh[ns][0], bh[ns][1]);
                }
        }

        if (has_next) {
            const int nb = buf ^ 1;
#pragma unroll
            for (int t = 0; t < 4; t++)
#pragma unroll
                for (int u = 0; u < 2; u++)
                    *(uint4*)(dyn + nb * (4 * TILE_B) + t * TILE_B +
                              ((r_ld + u * 64) * TS + c_ld) * 2) = stage[t][u];
            __syncthreads();
        }
    }

    // ---------------- epilogue ----------------
    const int qrow = lane >> 2;             // 0..7
    const int qcol = (lane & 3) * 2;
#pragma unroll
    for (int ms = 0; ms < 2; ms++) {
#pragma unroll
        for (int ns = 0; ns < 8; ns++) {
            const int ncol = n0 + wn + ns * 8 + qcol;
            const float b0 = bias[ncol], b1 = bias[ncol + 1];
#pragma unroll
            for (int half = 0; half < 2; half++) {
                const int m = m0 + wm + ms * 16 + qrow + half * 8;
                float2 v2 = make_float2(acc[ms][ns][2 * half] + b0,
                                        acc[ms][ns][2 * half + 1] + b1);
                if (is_fc) {
                    *(float2*)(g_fc + (size_t)m * DM + ncol) = v2;
                } else {
                    float* outp = (z == 0) ? g_q : (z == 1) ? g_k : g_v;
                    const int l = m >> 1, bb = m & 1;
                    const int h = ncol >> 6, dkb = ncol & 63;
                    *(float2*)(outp + ((size_t)(h * NB + bb) * L_SEQ + l) * DHEAD + dkb) = v2;
                }
            }
        }
    }
}

// =========================================================================
// Banded attention (FFMA). Epilogue writes attnout directly as bf16 hi/lo.
// =========================================================================
#define QS_STRIDE 132
#define VS_STRIDE 68
#define PH_STRIDE 66
#define QS_FLOATS (64 * QS_STRIDE)
#define KV_FLOATS 8704
#define PS_FLOATS (128 * PH_STRIDE)
#define ATTN_SMEM_BYTES ((QS_FLOATS + KV_FLOATS + PS_FLOATS) * 4)

__global__ void __launch_bounds__(256, 2)
attn_kernel(float* __restrict__ attn_raw)
{
    extern __shared__ float smx[];
    float* Qs  = smx;
    float* KVs = smx + QS_FLOATS;
    float* Ps  = smx + QS_FLOATS + KV_FLOATS;

    const int tid = threadIdx.x;
    const int tx = tid & 15, ty = tid >> 4;
    const int i0 = blockIdx.x * 128;
    const int hb = blockIdx.y;

    const float* Qg = g_q + (size_t)hb * L_SEQ * DHEAD;
    const float* Kg = g_k + (size_t)hb * L_SEQ * DHEAD;
    const float* Vg = g_v + (size_t)hb * L_SEQ * DHEAD;
    float* rawbase = attn_raw + (size_t)hb * L_SEQ * L_SEQ;

    {
        const float* src = Qg + (size_t)i0 * DHEAD;
        for (int idx = tid; idx < 128 * 16; idx += 256) {
            int r = idx >> 4, kq = (idx & 15) << 2;
            float4 v = *(const float4*)&src[r * 64 + kq];
            Qs[(kq + 0) * QS_STRIDE + r] = v.x;
            Qs[(kq + 1) * QS_STRIDE + r] = v.y;
            Qs[(kq + 2) * QS_STRIDE + r] = v.z;
            Qs[(kq + 3) * QS_STRIDE + r] = v.w;
        }
    }

    float rm[8];
#pragma unroll
    for (int r = 0; r < 8; r++) rm[r] = -FLT_MAX;

    const int ibase = i0 + ty * 8;

    for (int cch = 0; cch < 3; cch++) {
        int j0 = i0 + (cch - 1) * 128;
        if (j0 < 0 || j0 >= L_SEQ) continue;
        __syncthreads();
        {
            const float* src = Kg + (size_t)j0 * DHEAD;
            for (int idx = tid; idx < 128 * 16; idx += 256) {
                int r = idx >> 4, kq = (idx & 15) << 2;
                float4 v = *(const float4*)&src[r * 64 + kq];
                KVs[(kq + 0) * QS_STRIDE + r] = v.x;
                KVs[(kq + 1) * QS_STRIDE + r] = v.y;
                KVs[(kq + 2) * QS_STRIDE + r] = v.z;
                KVs[(kq + 3) * QS_STRIDE + r] = v.w;
            }
        }
        __syncthreads();
        float s[8][8];
#pragma unroll
        for (int r = 0; r < 8; r++)
#pragma unroll
            for (int c = 0; c < 8; c++) s[r][c] = 0.f;

        for (int kk = 0; kk < 64; kk++) {
            float a[8], b[8];
            *(float4*)&a[0] = *(const float4*)&Qs[kk * QS_STRIDE + ty * 8];
            *(float4*)&a[4] = *(const float4*)&Qs[kk * QS_STRIDE + ty * 8 + 4];
            *(float4*)&b[0] = *(const float4*)&KVs[kk * QS_STRIDE + tx * 8];
            *(float4*)&b[4] = *(const float4*)&KVs[kk * QS_STRIDE + tx * 8 + 4];
#pragma unroll
            for (int r = 0; r < 8; r++)
#pragma unroll
                for (int c = 0; c < 8; c++)
                    s[r][c] = fmaf(a[r], b[c], s[r][c]);
        }
        const int jbase = j0 + tx * 8;
#pragma unroll
        for (int r = 0; r < 8; r++) {
            int i = ibase + r;
            float* rowp = rawbase + (size_t)i * L_SEQ;
#pragma unroll
            for (int c2 = 0; c2 < 8; c2++) {
                int j = jbase + c2;
                int d = i - j;
                if (d >= -SPAN_W && d <= SPAN_W) {
                    float v = s[r][c2] * 0.125f;
                    rowp[j] = v;
                    rm[r] = fmaxf(rm[r], v);
                }
            }
        }
    }

#pragma unroll
    for (int r = 0; r < 8; r++) {
#pragma unroll
        for (int off = 8; off > 0; off >>= 1)
            rm[r] = fmaxf(rm[r], __shfl_xor_sync(0xffffffffu, rm[r], off, 16));
    }

    float O[8][4];
    float ll[8];
#pragma unroll
    for (int r = 0; r < 8; r++) {
        ll[r] = 0.f;
#pragma unroll
        for (int c = 0; c < 4; c++) O[r][c] = 0.f;
    }

    for (int cch = 0; cch < 3; cch++) {
        int j0 = i0 + (cch - 1) * 128;
        if (j0 < 0 || j0 >= L_SEQ) continue;
        __syncthreads();
        {
            const float* src = Vg + (size_t)j0 * DHEAD;
            for (int idx = tid; idx < 128 * 16; idx += 256) {
                int r = idx >> 4, kq = (idx & 15) << 2;
                *(float4*)&KVs[r * VS_STRIDE + kq] = *(const float4*)&src[r * 64 + kq];
            }
        }
        __syncthreads();

#pragma unroll
        for (int half = 0; half < 2; half++) {
            if ((tx >> 3) == half) {
                const int txh = tx & 7;
                const int jbase = j0 + tx * 8;
#pragma unroll
                for (int r = 0; r < 8; r++) {
                    int i = ibase + r;
                    const float* rowp = rawbase + (size_t)i * L_SEQ;
                    float* prow = Ps + (size_t)(ty * 8 + r) * PH_STRIDE + txh * 8;
#pragma unroll
                    for (int c2 = 0; c2 < 8; c2++) {
                        int j = jbase + c2;
                        int d = i - j;
                        float p = 0.f;
                        if (d >= -SPAN_W && d <= SPAN_W)
                            p = __expf(rowp[j] - rm[r]);
                        ll[r] += p;
                        prow[c2] = p;
                    }
                }
            }
            __syncthreads();
            const int joff = half * 64;
            for (int jj = 0; jj < 64; jj++) {
                float4 v4 = *(const float4*)&KVs[(jj + joff) * VS_STRIDE + tx * 4];
#pragma unroll
                for (int r = 0; r < 8; r++) {
                    float pv = Ps[(size_t)(ty * 8 + r) * PH_STRIDE + jj];
                    O[r][0] = fmaf(pv, v4.x, O[r][0]);
                    O[r][1] = fmaf(pv, v4.y, O[r][1]);
                    O[r][2] = fmaf(pv, v4.z, O[r][2]);
                    O[r][3] = fmaf(pv, v4.w, O[r][3]);
                }
            }
            if (half == 0) __syncthreads();
        }
    }

#pragma unroll
    for (int r = 0; r < 8; r++) {
#pragma unroll
        for (int off = 8; off > 0; off >>= 1)
            ll[r] += __shfl_xor_sync(0xffffffffu, ll[r], off, 16);
    }

    const int h = hb >> 1, bb = hb & 1;
#pragma unroll
    for (int r = 0; r < 8; r++) {
        int i = ibase + r;
        float inv = 1.f / ll[r];
        float vs[4] = {O[r][0] * inv, O[r][1] * inv, O[r][2] * inv, O[r][3] * inv};
        __nv_bfloat16 hi[4], lo[4];
#pragma unroll
        for (int c = 0; c < 4; c++) {
            hi[c] = __float2bfloat16(vs[c]);
            lo[c] = __float2bfloat16(vs[c] - __bfloat162float(hi[c]));
        }
        size_t oidx = ((size_t)i * NB + bb) * DM + h * DHEAD + tx * 4;
        *(uint2*)(g_aohi + oidx) = *(uint2*)hi;
        *(uint2*)(g_aolo + oidx) = *(uint2*)lo;
        if (tx == 0) {
            g_rowm[hb * L_SEQ + i] = rm[r];
            g_rowl[hb * L_SEQ + i] = ll[r];
        }
    }
}

// =========================================================================
// Normalize raw scores -> softmax weights; zero out-of-band.
// =========================================================================
__global__ void __launch_bounds__(256)
attn_norm_kernel(float* __restrict__ attn)
{
    const int row = blockIdx.x;
    const int i = row & (L_SEQ - 1);
    const float m = g_rowm[row];
    const float inv = 1.f / g_rowl[row];
    float* p = attn + (size_t)row * L_SEQ;
    const int j0 = threadIdx.x * 8;
    float out[8];
#pragma unroll
    for (int u = 0; u < 8; u++) {
        int j = j0 + u;
        int d = i - j;
        float raw = 0.f;
        bool inband = (d >= -SPAN_W && d <= SPAN_W);
        if (inband) raw = p[j];
        out[u] = inband ? __expf(raw - m) * inv : 0.f;
    }
    *(float4*)&p[j0]     = make_float4(out[0], out[1], out[2], out[3]);
    *(float4*)&p[j0 + 4] = make_float4(out[4], out[5], out[6], out[7]);
}

// =========================================================================
// Residual + LayerNorm.
// =========================================================================
__global__ void __launch_bounds__(256)
ln_kernel(const float* __restrict__ query, const float* __restrict__ gamma,
          const float* __restrict__ beta, float* __restrict__ y)
{
    __shared__ float red[16];
    const int row = blockIdx.x;
    const int t = threadIdx.x;

    float4 f = *(const float4*)&g_fc[(size_t)row * DM + t * 4];
    float4 q = *(const float4*)&query[(size_t)row * DM + t * 4];
    float v0 = f.x + q.x, v1 = f.y + q.y, v2 = f.z + q.z, v3 = f.w + q.w;

    float s = v0 + v1 + v2 + v3;
    float s2 = v0 * v0 + v1 * v1 + v2 * v2 + v3 * v3;
#pragma unroll
    for (int off = 16; off > 0; off >>= 1) {
        s  += __shfl_xor_sync(0xffffffffu, s, off);
        s2 += __shfl_xor_sync(0xffffffffu, s2, off);
    }
    const int warp = t >> 5, lane = t & 31;
    if (lane == 0) { red[warp] = s; red[warp + 8] = s2; }
    __syncthreads();
    if (t < 32) {
        float a  = (lane < 8) ? red[lane] : 0.f;
        float b2 = (lane < 8) ? red[lane + 8] : 0.f;
#pragma unroll
        for (int off = 4; off > 0; off >>= 1) {
            a  += __shfl_xor_sync(0xffffffffu, a, off);
            b2 += __shfl_xor_sync(0xffffffffu, b2, off);
        }
        if (lane == 0) { red[0] = a; red[1] = b2; }
    }
    __syncthreads();
    const float mean = red[0] * (1.f / DM);
    const float var  = red[1] * (1.f / DM) - mean * mean;
    const float rstd = rsqrtf(var + 1e-5f);

    float4 g  = *(const float4*)&gamma[t * 4];
    float4 be = *(const float4*)&beta[t * 4];
    float4 o;
    o.x = (v0 - mean) * rstd * g.x + be.x;
    o.y = (v1 - mean) * rstd * g.y + be.y;
    o.z = (v2 - mean) * rstd * g.z + be.z;
    o.w = (v3 - mean) * rstd * g.w + be.w;
    *(float4*)&y[(size_t)row * DM + t * 4] = o;
}

// =========================================================================
extern "C" void kernel_launch(void* const* d_in, const int* in_sizes, int n_in,
                              void* d_out, int out_size)
{
    const float* query = (const float*)d_in[0];
    const float* key   = (const float*)d_in[1];
    const float* value = (const float*)d_in[2];
    const float* Wq    = (const float*)d_in[3];
    const float* bq    = (const float*)d_in[4];
    const float* Wk    = (const float*)d_in[5];
    const float* bk    = (const float*)d_in[6];
    const float* Wv    = (const float*)d_in[7];
    const float* bv    = (const float*)d_in[8];
    const float* Wfc   = (const float*)d_in[9];
    const float* bfc   = (const float*)d_in[10];
    const float* gamma = (const float*)d_in[11];
    const float* beta  = (const float*)d_in[12];

    float* y_out = (float*)d_out;
    float* attn_out = y_out + (size_t)L_SEQ * NB * DM;

    cudaFuncSetAttribute(attn_kernel,
                         cudaFuncAttributeMaxDynamicSharedMemorySize,
                         ATTN_SMEM_BYTES);
    cudaFuncSetAttribute(mma_gemm_kernel,
                         cudaFuncAttributeMaxDynamicSharedMemorySize,
                         GEMM_SMEM_BYTES);

    conv_w_kernel<<<dim3(DM / 32, DM / 32, 4), 256>>>(Wq, Wk, Wv, Wfc);
    conv_in_kernel<<<dim3(MROWS * DM / 2048, 3), 256>>>(query, key, value);

    mma_gemm_kernel<<<dim3(MROWS / 128, DM / 128, 3), 256, GEMM_SMEM_BYTES>>>(
        bq, bk, bv, bfc, 0);

    attn_kernel<<<dim3(L_SEQ / 128, HB), 256, ATTN_SMEM_BYTES>>>(attn_out);

    mma_gemm_kernel<<<dim3(MROWS / 128, DM / 128, 1), 256, GEMM_SMEM_BYTES>>>(
        bq, bk, bv, bfc, 1);

    ln_kernel<<<MROWS, 256>>>(query, gamma, beta, y_out);

    attn_norm_kernel<<<HB * L_SEQ, 256>>>(attn_out);
}

// round 6
// speedup vs baseline: 2.2712x; 1.1958x over previous
#include <cuda_runtime.h>
#include <cuda_bf16.h>
#include <math.h>
#include <float.h>
#include <stdint.h>

#define L_SEQ 2048
#define NB 2
#define DM 1024
#define NH 16
#define DHEAD 64
#define SPAN_W 128
#define MROWS (L_SEQ * NB)          // 4096
#define HB (NH * NB)                // 32

// ---------------- static scratch (no allocations allowed) ----------------
__device__ float g_fc[MROWS * DM];               // FC output (pre-LN)
__device__ float g_rowl[HB * L_SEQ];             // softmax row sum

// bf16 split operands
__device__ __nv_bfloat16 g_inhi[3][MROWS * DM];  // q/k/v inputs hi
__device__ __nv_bfloat16 g_inlo[3][MROWS * DM];  // lo
__device__ __nv_bfloat16 g_wthi[4][DM * DM];     // W^T [n][k] hi
__device__ __nv_bfloat16 g_wtlo[4][DM * DM];     // lo
__device__ __nv_bfloat16 g_aohi[MROWS * DM];     // attnout hi
__device__ __nv_bfloat16 g_aolo[MROWS * DM];     // attnout lo
// projected Q (x0.125) / K, head-major [hb][l][dk], bf16 hi/lo
__device__ __nv_bfloat16 g_qkhi[2][HB * L_SEQ * DHEAD];
__device__ __nv_bfloat16 g_qklo[2][HB * L_SEQ * DHEAD];
// projected V transposed [hb][dv][l], bf16 hi/lo
__device__ __nv_bfloat16 g_vthi[HB * DHEAD * L_SEQ];
__device__ __nv_bfloat16 g_vtlo[HB * DHEAD * L_SEQ];

// ---------------- helpers ----------------
__device__ __forceinline__ uint32_t smem_u32(const void* p) {
    uint32_t a;
    asm("{ .reg .u64 t; cvta.to.shared.u64 t, %1; cvt.u32.u64 %0, t; }"
        : "=r"(a) : "l"(p));
    return a;
}
__device__ __forceinline__ void ldsm4(uint32_t (&r)[4], uint32_t addr) {
    asm volatile("ldmatrix.sync.aligned.m8n8.x4.shared.b16 {%0,%1,%2,%3}, [%4];"
                 : "=r"(r[0]), "=r"(r[1]), "=r"(r[2]), "=r"(r[3]) : "r"(addr));
}
__device__ __forceinline__ void mma_bf16(float (&d)[4], const uint32_t (&a)[4],
                                         uint32_t b0, uint32_t b1) {
    asm volatile(
        "mma.sync.aligned.m16n8k16.row.col.f32.bf16.bf16.f32 "
        "{%0,%1,%2,%3}, {%4,%5,%6,%7}, {%8,%9}, {%0,%1,%2,%3};"
        : "+f"(d[0]), "+f"(d[1]), "+f"(d[2]), "+f"(d[3])
        : "r"(a[0]), "r"(a[1]), "r"(a[2]), "r"(a[3]), "r"(b0), "r"(b1));
}
// fast exp on FMA pipe (x <= 0), ~1e-7 rel
__device__ __forceinline__ float fexp(float x) {
    x = fmaxf(x, -80.f);
    float t = fmaf(x, 1.4426950408889634f, 12582912.f);
    float n = t - 12582912.f;
    float f = fmaf(n, -0.693145751953125f, x);
    f = fmaf(n, -1.428606765330187e-06f, f);
    float p = 1.3888889e-3f;
    p = fmaf(p, f, 8.3333338e-3f);
    p = fmaf(p, f, 4.1666668e-2f);
    p = fmaf(p, f, 1.6666667e-1f);
    p = fmaf(p, f, 5.0e-1f);
    p = fmaf(p, f, 1.0f);
    p = fmaf(p, f, 1.0f);
    int i = (int)n;
    return __int_as_float(__float_as_int(p) + (i << 23));
}
__device__ __forceinline__ uint32_t packbf(float a, float b) {
    __nv_bfloat162 t = __floats2bfloat162_rn(a, b);
    return *reinterpret_cast<uint32_t*>(&t);
}

// ======================== converter kernels ==============================
__global__ void __launch_bounds__(256)
conv_in_kernel(const float* __restrict__ q, const float* __restrict__ k,
               const float* __restrict__ v)
{
    const int z = blockIdx.y;
    const float* src = (z == 0) ? q : (z == 1) ? k : v;
    __nv_bfloat16* dhi = g_inhi[z];
    __nv_bfloat16* dlo = g_inlo[z];
    size_t base = ((size_t)blockIdx.x * 256 + threadIdx.x) * 8;
    float4 a = *(const float4*)(src + base);
    float4 b = *(const float4*)(src + base + 4);
    __nv_bfloat16 hi[8], lo[8];
    float xs[8] = {a.x, a.y, a.z, a.w, b.x, b.y, b.z, b.w};
#pragma unroll
    for (int i = 0; i < 8; i++) {
        hi[i] = __float2bfloat16(xs[i]);
        lo[i] = __float2bfloat16(xs[i] - __bfloat162float(hi[i]));
    }
    *(uint4*)(dhi + base) = *(uint4*)hi;
    *(uint4*)(dlo + base) = *(uint4*)lo;
}

__global__ void __launch_bounds__(256)
conv_w_kernel(const float* __restrict__ Wq, const float* __restrict__ Wk,
              const float* __restrict__ Wv, const float* __restrict__ Wfc)
{
    __shared__ float tile[32][33];
    const int z = blockIdx.z;
    const float* W = (z == 0) ? Wq : (z == 1) ? Wk : (z == 2) ? Wv : Wfc;
    __nv_bfloat16* dhi = g_wthi[z];
    __nv_bfloat16* dlo = g_wtlo[z];
    const int n0 = blockIdx.x * 32, k0 = blockIdx.y * 32;
    const int c = threadIdx.x & 31, r0 = (threadIdx.x >> 5) * 4;
#pragma unroll
    for (int rr = 0; rr < 4; rr++)
        tile[r0 + rr][c] = W[(size_t)(k0 + r0 + rr) * DM + n0 + c];
    __syncthreads();
#pragma unroll
    for (int rr = 0; rr < 4; rr++) {
        int n = n0 + r0 + rr;
        float x = tile[c][r0 + rr];
        __nv_bfloat16 hi = __float2bfloat16(x);
        __nv_bfloat16 lo = __float2bfloat16(x - __bfloat162float(hi));
        dhi[(size_t)n * DM + k0 + c] = hi;
        dlo[(size_t)n * DM + k0 + c] = lo;
    }
}

// ======================== split-bf16 HMMA GEMM ===========================
#define TSX 40
#define TILE_B (128 * TSX * 2)
#define GEMM_SMEM_BYTES (2 * 4 * TILE_B)   // 81920

__global__ void __launch_bounds__(256, 1)
mma_gemm_kernel(const float* __restrict__ bq, const float* __restrict__ bk,
                const float* __restrict__ bv, const float* __restrict__ bfc,
                int is_fc)
{
    extern __shared__ char dyn[];
    const uint32_t sb = smem_u32(dyn);
    const int tid = threadIdx.x, wid = tid >> 5, lane = tid & 31;
    const int m0 = blockIdx.x * 128, n0 = blockIdx.y * 128;
    const int z = blockIdx.z;

    const __nv_bfloat16 *Ah, *Al, *Bh, *Bl;
    const float* bias;
    if (is_fc) {
        Ah = g_aohi; Al = g_aolo; Bh = g_wthi[3]; Bl = g_wtlo[3]; bias = bfc;
    } else {
        Ah = g_inhi[z]; Al = g_inlo[z]; Bh = g_wthi[z]; Bl = g_wtlo[z];
        bias = (z == 0) ? bq : (z == 1) ? bk : bv;
    }
    const __nv_bfloat16* srcs[4] = {
        Ah + (size_t)m0 * DM, Al + (size_t)m0 * DM,
        Bh + (size_t)n0 * DM, Bl + (size_t)n0 * DM };

    const int wm = (wid & 3) * 32;
    const int wn = (wid >> 2) * 64;

    float acc[2][8][4];
#pragma unroll
    for (int ms = 0; ms < 2; ms++)
#pragma unroll
        for (int ns = 0; ns < 8; ns++)
#pragma unroll
            for (int c = 0; c < 4; c++) acc[ms][ns][c] = 0.f;

    const int r_ld = tid >> 2;
    const int c_ld = (tid & 3) * 8;

    uint4 stage[4][2];
#pragma unroll
    for (int t = 0; t < 4; t++)
#pragma unroll
        for (int u = 0; u < 2; u++)
            stage[t][u] = *(const uint4*)(srcs[t] + (size_t)(r_ld + u * 64) * DM + c_ld);
#pragma unroll
    for (int t = 0; t < 4; t++)
#pragma unroll
        for (int u = 0; u < 2; u++)
            *(uint4*)(dyn + t * TILE_B + ((r_ld + u * 64) * TSX + c_ld) * 2) = stage[t][u];
    __syncthreads();

    const int rowA = wm + (lane & 15);
    const int colA = (lane >> 4) << 3;
    const int rowB = wn + (lane & 7) + ((lane >> 4) << 3);
    const int colB = ((lane >> 3) & 1) << 3;

    for (int step = 0; step < 32; step++) {
        const int buf = step & 1;
        const uint32_t base = sb + buf * (4 * TILE_B);
        const int has_next = (step + 1 < 32);
        if (has_next) {
            const int k0 = (step + 1) * 32;
#pragma unroll
            for (int t = 0; t < 4; t++)
#pragma unroll
                for (int u = 0; u < 2; u++)
                    stage[t][u] = *(const uint4*)(srcs[t] + (size_t)(r_ld + u * 64) * DM + k0 + c_ld);
        }
#pragma unroll
        for (int kh = 0; kh < 32; kh += 16) {
            uint32_t ah[2][4], al[2][4];
#pragma unroll
            for (int ms = 0; ms < 2; ms++) {
                uint32_t off = ((rowA + ms * 16) * TSX + kh + colA) * 2;
                ldsm4(ah[ms], base + 0 * TILE_B + off);
                ldsm4(al[ms], base + 1 * TILE_B + off);
            }
            uint32_t bh[8][2], bl[8][2];
#pragma unroll
            for (int np = 0; np < 4; np++) {
                uint32_t off = ((rowB + np * 16) * TSX + kh + colB) * 2;
                uint32_t t4[4];
                ldsm4(t4, base + 2 * TILE_B + off);
                bh[2 * np][0] = t4[0]; bh[2 * np][1] = t4[1];
                bh[2 * np + 1][0] = t4[2]; bh[2 * np + 1][1] = t4[3];
                ldsm4(t4, base + 3 * TILE_B + off);
                bl[2 * np][0] = t4[0]; bl[2 * np][1] = t4[1];
                bl[2 * np + 1][0] = t4[2]; bl[2 * np + 1][1] = t4[3];
            }
#pragma unroll
            for (int ms = 0; ms < 2; ms++)
#pragma unroll
                for (int ns = 0; ns < 8; ns++) {
                    mma_bf16(acc[ms][ns], ah[ms], bh[ns][0], bh[ns][1]);
                    mma_bf16(acc[ms][ns], ah[ms], bl[ns][0], bl[ns][1]);
                    mma_bf16(acc[ms][ns], al[ms], bh[ns][0], bh[ns][1]);
                }
        }
        if (has_next) {
            const int nb = buf ^ 1;
#pragma unroll
            for (int t = 0; t < 4; t++)
#pragma unroll
                for (int u = 0; u < 2; u++)
                    *(uint4*)(dyn + nb * (4 * TILE_B) + t * TILE_B +
                              ((r_ld + u * 64) * TSX + c_ld) * 2) = stage[t][u];
            __syncthreads();
        }
    }

    const int qrow = lane >> 2;
    const int qcol = (lane & 3) * 2;
    const float scale = (!is_fc && z == 0) ? 0.125f : 1.0f;
#pragma unroll
    for (int ms = 0; ms < 2; ms++) {
#pragma unroll
        for (int ns = 0; ns < 8; ns++) {
            const int ncol = n0 + wn + ns * 8 + qcol;
            const float b0 = bias[ncol], b1 = bias[ncol + 1];
#pragma unroll
            for (int half = 0; half < 2; half++) {
                const int m = m0 + wm + ms * 16 + qrow + half * 8;
                float x0 = (acc[ms][ns][2 * half] + b0) * scale;
                float x1 = (acc[ms][ns][2 * half + 1] + b1) * scale;
                if (is_fc) {
                    *(float2*)(g_fc + (size_t)m * DM + ncol) = make_float2(x0, x1);
                } else {
                    const int l = m >> 1, bb = m & 1;
                    const int h = ncol >> 6, dkb = ncol & 63;
                    __nv_bfloat16 h0 = __float2bfloat16(x0);
                    __nv_bfloat16 l0 = __float2bfloat16(x0 - __bfloat162float(h0));
                    __nv_bfloat16 h1 = __float2bfloat16(x1);
                    __nv_bfloat16 l1 = __float2bfloat16(x1 - __bfloat162float(h1));
                    if (z < 2) {
                        size_t idx = ((size_t)(h * NB + bb) * L_SEQ + l) * DHEAD + dkb;
                        __nv_bfloat162 ph = __halves2bfloat162(h0, h1);
                        __nv_bfloat162 pl = __halves2bfloat162(l0, l1);
                        *(uint32_t*)(g_qkhi[z] + idx) = *(uint32_t*)&ph;
                        *(uint32_t*)(g_qklo[z] + idx) = *(uint32_t*)&pl;
                    } else {
                        size_t base2 = ((size_t)(h * NB + bb) * DHEAD + dkb) * L_SEQ + l;
                        g_vthi[base2] = h0;          g_vtlo[base2] = l0;
                        g_vthi[base2 + L_SEQ] = h1;  g_vtlo[base2 + L_SEQ] = l1;
                    }
                }
            }
        }
    }
}

// =========================================================================
// HMMA banded attention.  Block = (iblock 128, hb), 8 warps x 16 rows.
// Pass A: S = Q K^T (3-term bf16), row max.  Pass B: recompute S,
// p = fexp(s-m) -> gmem (unnormalized) + smem bf16 hi/lo, O = P V (3-term).
// =========================================================================
#define QKS 72           // Q/K smem row stride (bf16)
#define VTS 136          // Vt smem row stride
#define PSS 136          // P smem row stride
#define OFF_QH 0
#define OFF_QL 18432
#define OFF_KH 36864
#define OFF_KL 55296
#define OFF_VH 73728
#define OFF_VL 91136
#define OFF_PH 108544
#define OFF_PL 143360
#define ATTN_SMEM_BYTES 178176

struct SFrag { float v[16][4]; };

__device__ __forceinline__ void compute_S(const char* dyn, uint32_t sb,
                                          int lane, int w16, SFrag& S)
{
#pragma unroll
    for (int n = 0; n < 16; n++)
#pragma unroll
        for (int e = 0; e < 4; e++) S.v[n][e] = 0.f;
    const uint32_t aoff = ((w16 + (lane & 15)) * QKS + ((lane >> 4) << 3)) * 2;
    const uint32_t brow = (lane & 7) + ((lane >> 4) << 3);
    const uint32_t bcol = ((lane >> 3) & 1) << 3;
#pragma unroll
    for (int ks = 0; ks < 4; ks++) {
        uint32_t ah[4], al[4];
        ldsm4(ah, sb + OFF_QH + aoff + ks * 32);
        ldsm4(al, sb + OFF_QL + aoff + ks * 32);
#pragma unroll
        for (int n2 = 0; n2 < 8; n2++) {
            uint32_t off = ((n2 * 16 + brow) * QKS + ks * 16 + bcol) * 2;
            uint32_t kh[4], kl[4];
            ldsm4(kh, sb + OFF_KH + off);
            ldsm4(kl, sb + OFF_KL + off);
            mma_bf16(S.v[2 * n2], ah, kh[0], kh[1]);
            mma_bf16(S.v[2 * n2], ah, kl[0], kl[1]);
            mma_bf16(S.v[2 * n2], al, kh[0], kh[1]);
            mma_bf16(S.v[2 * n2 + 1], ah, kh[2], kh[3]);
            mma_bf16(S.v[2 * n2 + 1], ah, kl[2], kl[3]);
            mma_bf16(S.v[2 * n2 + 1], al, kh[2], kh[3]);
        }
    }
}

__global__ void __launch_bounds__(256)
attn_kernel(float* __restrict__ attn_raw)
{
    extern __shared__ char dyn[];
    const uint32_t sb = smem_u32(dyn);
    const int tid = threadIdx.x, wid = tid >> 5, lane = tid & 31;
    const int w16 = wid * 16;
    const int i0 = blockIdx.x * 128;
    const int hb = blockIdx.y;

    const __nv_bfloat16* Qh = g_qkhi[0] + (size_t)hb * L_SEQ * DHEAD;
    const __nv_bfloat16* Ql = g_qklo[0] + (size_t)hb * L_SEQ * DHEAD;
    const __nv_bfloat16* Kh = g_qkhi[1] + (size_t)hb * L_SEQ * DHEAD;
    const __nv_bfloat16* Kl = g_qklo[1] + (size_t)hb * L_SEQ * DHEAD;
    const __nv_bfloat16* Vh = g_vthi + (size_t)hb * DHEAD * L_SEQ;
    const __nv_bfloat16* Vl = g_vtlo + (size_t)hb * DHEAD * L_SEQ;
    float* rawbase = attn_raw + (size_t)hb * L_SEQ * L_SEQ;

    // load Q tile (persistent)
    {
        const __nv_bfloat16* src = Qh + (size_t)i0 * DHEAD;
        const __nv_bfloat16* srl = Ql + (size_t)i0 * DHEAD;
#pragma unroll
        for (int u = 0; u < 4; u++) {
            int idx = tid + u * 256;
            int r = idx >> 3, c = idx & 7;
            *(uint4*)(dyn + OFF_QH + (r * QKS + c * 8) * 2) =
                *(const uint4*)(src + (size_t)r * DHEAD + c * 8);
            *(uint4*)(dyn + OFF_QL + (r * QKS + c * 8) * 2) =
                *(const uint4*)(srl + (size_t)r * DHEAD + c * 8);
        }
    }

    const int ir0 = i0 + w16 + (lane >> 2);
    const int ir1 = ir0 + 8;
    const int jco = 2 * (lane & 3);

    // ---------------- Pass A: row max ----------------
    float m0 = -1e30f, m1 = -1e30f;
    for (int cch = 0; cch < 3; cch++) {
        int j0 = i0 + (cch - 1) * 128;
        if (j0 < 0 || j0 >= L_SEQ) continue;
        __syncthreads();
#pragma unroll
        for (int u = 0; u < 4; u++) {
            int idx = tid + u * 256;
            int r = idx >> 3, c = idx & 7;
            *(uint4*)(dyn + OFF_KH + (r * QKS + c * 8) * 2) =
                *(const uint4*)(Kh + (size_t)(j0 + r) * DHEAD + c * 8);
            *(uint4*)(dyn + OFF_KL + (r * QKS + c * 8) * 2) =
                *(const uint4*)(Kl + (size_t)(j0 + r) * DHEAD + c * 8);
        }
        __syncthreads();
        SFrag S;
        compute_S(dyn, sb, lane, w16, S);
#pragma unroll
        for (int n = 0; n < 16; n++) {
            int j = j0 + n * 8 + jco;
            int d00 = ir0 - j, d01 = ir0 - j - 1;
            int d10 = ir1 - j, d11 = ir1 - j - 1;
            if (d00 >= -SPAN_W && d00 <= SPAN_W) m0 = fmaxf(m0, S.v[n][0]);
            if (d01 >= -SPAN_W && d01 <= SPAN_W) m0 = fmaxf(m0, S.v[n][1]);
            if (d10 >= -SPAN_W && d10 <= SPAN_W) m1 = fmaxf(m1, S.v[n][2]);
            if (d11 >= -SPAN_W && d11 <= SPAN_W) m1 = fmaxf(m1, S.v[n][3]);
        }
    }
    m0 = fmaxf(m0, __shfl_xor_sync(0xffffffffu, m0, 1));
    m0 = fmaxf(m0, __shfl_xor_sync(0xffffffffu, m0, 2));
    m1 = fmaxf(m1, __shfl_xor_sync(0xffffffffu, m1, 1));
    m1 = fmaxf(m1, __shfl_xor_sync(0xffffffffu, m1, 2));

    // ---------------- Pass B ----------------
    float O[8][4];
#pragma unroll
    for (int n = 0; n < 8; n++)
#pragma unroll
        for (int e = 0; e < 4; e++) O[n][e] = 0.f;
    float sum0 = 0.f, sum1 = 0.f;

    for (int cch = 0; cch < 3; cch++) {
        int j0 = i0 + (cch - 1) * 128;
        if (j0 < 0 || j0 >= L_SEQ) continue;
        __syncthreads();     // prev chunk K/V/P fully consumed
        {
#pragma unroll
            for (int u = 0; u < 4; u++) {
                int idx = tid + u * 256;
                int r = idx >> 3, c = idx & 7;
                *(uint4*)(dyn + OFF_KH + (r * QKS + c * 8) * 2) =
                    *(const uint4*)(Kh + (size_t)(j0 + r) * DHEAD + c * 8);
                *(uint4*)(dyn + OFF_KL + (r * QKS + c * 8) * 2) =
                    *(const uint4*)(Kl + (size_t)(j0 + r) * DHEAD + c * 8);
            }
#pragma unroll
            for (int u = 0; u < 4; u++) {
                int idx = tid + u * 256;
                int r = idx >> 4, c = idx & 15;
                *(uint4*)(dyn + OFF_VH + (r * VTS + c * 8) * 2) =
                    *(const uint4*)(Vh + (size_t)r * L_SEQ + j0 + c * 8);
                *(uint4*)(dyn + OFF_VL + (r * VTS + c * 8) * 2) =
                    *(const uint4*)(Vl + (size_t)r * L_SEQ + j0 + c * 8);
            }
        }
        __syncthreads();
        SFrag S;
        compute_S(dyn, sb, lane, w16, S);

        // exp + stores
#pragma unroll
        for (int n = 0; n < 16; n++) {
            int j = j0 + n * 8 + jco;
            int d00 = ir0 - j, d01 = ir0 - j - 1;
            int d10 = ir1 - j, d11 = ir1 - j - 1;
            float p00 = (d00 >= -SPAN_W && d00 <= SPAN_W) ? fexp(S.v[n][0] - m0) : 0.f;
            float p01 = (d01 >= -SPAN_W && d01 <= SPAN_W) ? fexp(S.v[n][1] - m0) : 0.f;
            float p10 = (d10 >= -SPAN_W && d10 <= SPAN_W) ? fexp(S.v[n][2] - m1) : 0.f;
            float p11 = (d11 >= -SPAN_W && d11 <= SPAN_W) ? fexp(S.v[n][3] - m1) : 0.f;
            sum0 += p00 + p01;
            sum1 += p10 + p11;
            *(float2*)(rawbase + (size_t)ir0 * L_SEQ + j) = make_float2(p00, p01);
            *(float2*)(rawbase + (size_t)ir1 * L_SEQ + j) = make_float2(p10, p11);
            // smem P (bf16 hi/lo)
            __nv_bfloat16 h00 = __float2bfloat16(p00);
            __nv_bfloat16 h01 = __float2bfloat16(p01);
            __nv_bfloat16 h10 = __float2bfloat16(p10);
            __nv_bfloat16 h11 = __float2bfloat16(p11);
            uint32_t col = n * 8 + jco;
            uint32_t r0off = ((w16 + (lane >> 2)) * PSS + col) * 2;
            uint32_t r1off = ((w16 + (lane >> 2) + 8) * PSS + col) * 2;
            *(uint32_t*)(dyn + OFF_PH + r0off) = packbf(__bfloat162float(h00), __bfloat162float(h01));
            *(uint32_t*)(dyn + OFF_PH + r1off) = packbf(__bfloat162float(h10), __bfloat162float(h11));
            *(uint32_t*)(dyn + OFF_PL + r0off) =
                packbf(p00 - __bfloat162float(h00), p01 - __bfloat162float(h01));
            *(uint32_t*)(dyn + OFF_PL + r1off) =
                packbf(p10 - __bfloat162float(h10), p11 - __bfloat162float(h11));
        }
        __syncthreads();     // P ready

        // O += P @ V
        const uint32_t aoff = ((w16 + (lane & 15)) * PSS + ((lane >> 4) << 3)) * 2;
        const uint32_t brow = (lane & 7) + ((lane >> 4) << 3);
        const uint32_t bcol = ((lane >> 3) & 1) << 3;
#pragma unroll
        for (int ks = 0; ks < 8; ks++) {
            uint32_t aph[4], apl[4];
            ldsm4(aph, sb + OFF_PH + aoff + ks * 32);
            ldsm4(apl, sb + OFF_PL + aoff + ks * 32);
#pragma unroll
            for (int n2 = 0; n2 < 4; n2++) {
                uint32_t off = ((n2 * 16 + brow) * VTS + ks * 16 + bcol) * 2;
                uint32_t vh4[4], vl4[4];
                ldsm4(vh4, sb + OFF_VH + off);
                ldsm4(vl4, sb + OFF_VL + off);
                mma_bf16(O[2 * n2], aph, vh4[0], vh4[1]);
                mma_bf16(O[2 * n2], apl, vh4[0], vh4[1]);
                mma_bf16(O[2 * n2], aph, vl4[0], vl4[1]);
                mma_bf16(O[2 * n2 + 1], aph, vh4[2], vh4[3]);
                mma_bf16(O[2 * n2 + 1], apl, vh4[2], vh4[3]);
                mma_bf16(O[2 * n2 + 1], aph, vl4[2], vl4[3]);
            }
        }
    }

    sum0 += __shfl_xor_sync(0xffffffffu, sum0, 1);
    sum0 += __shfl_xor_sync(0xffffffffu, sum0, 2);
    sum1 += __shfl_xor_sync(0xffffffffu, sum1, 1);
    sum1 += __shfl_xor_sync(0xffffffffu, sum1, 2);
    const float inv0 = 1.f / sum0;
    const float inv1 = 1.f / sum1;
    if ((lane & 3) == 0) {
        g_rowl[hb * L_SEQ + ir0] = sum0;
        g_rowl[hb * L_SEQ + ir1] = sum1;
    }

    // epilogue: attnout bf16 hi/lo  [l b][h dv]
    const int h = hb >> 1, bb = hb & 1;
#pragma unroll
    for (int n = 0; n < 8; n++) {
        int dv = n * 8 + jco;
        float x0 = O[n][0] * inv0, x1 = O[n][1] * inv0;
        float y0 = O[n][2] * inv1, y1 = O[n][3] * inv1;
        __nv_bfloat16 hx0 = __float2bfloat16(x0), hx1 = __float2bfloat16(x1);
        __nv_bfloat16 hy0 = __float2bfloat16(y0), hy1 = __float2bfloat16(y1);
        size_t i0x = ((size_t)ir0 * NB + bb) * DM + h * DHEAD + dv;
        size_t i1x = ((size_t)ir1 * NB + bb) * DM + h * DHEAD + dv;
        *(uint32_t*)(g_aohi + i0x) = packbf(__bfloat162float(hx0), __bfloat162float(hx1));
        *(uint32_t*)(g_aohi + i1x) = packbf(__bfloat162float(hy0), __bfloat162float(hy1));
        *(uint32_t*)(g_aolo + i0x) =
            packbf(x0 - __bfloat162float(hx0), x1 - __bfloat162float(hx1));
        *(uint32_t*)(g_aolo + i1x) =
            packbf(y0 - __bfloat162float(hy0), y1 - __bfloat162float(hy1));
    }
}

// =========================================================================
// Normalize: p (unnormalized exp) * inv in band; zero elsewhere. No exp.
// =========================================================================
__global__ void __launch_bounds__(256)
attn_norm_kernel(float* __restrict__ attn)
{
    const int row = blockIdx.x;
    const int i = row & (L_SEQ - 1);
    const float inv = 1.f / g_rowl[row];
    float* p = attn + (size_t)row * L_SEQ;
    const int j0 = threadIdx.x * 8;
    float out[8];
#pragma unroll
    for (int u = 0; u < 8; u++) {
        int j = j0 + u;
        int d = i - j;
        bool inband = (d >= -SPAN_W && d <= SPAN_W);
        out[u] = inband ? p[j] * inv : 0.f;
    }
    *(float4*)&p[j0]     = make_float4(out[0], out[1], out[2], out[3]);
    *(float4*)&p[j0 + 4] = make_float4(out[4], out[5], out[6], out[7]);
}

// =========================================================================
// Residual + LayerNorm.
// =========================================================================
__global__ void __launch_bounds__(256)
ln_kernel(const float* __restrict__ query, const float* __restrict__ gamma,
          const float* __restrict__ beta, float* __restrict__ y)
{
    __shared__ float red[16];
    const int row = blockIdx.x;
    const int t = threadIdx.x;

    float4 f = *(const float4*)&g_fc[(size_t)row * DM + t * 4];
    float4 q = *(const float4*)&query[(size_t)row * DM + t * 4];
    float v0 = f.x + q.x, v1 = f.y + q.y, v2 = f.z + q.z, v3 = f.w + q.w;

    float s = v0 + v1 + v2 + v3;
    float s2 = v0 * v0 + v1 * v1 + v2 * v2 + v3 * v3;
#pragma unroll
    for (int off = 16; off > 0; off >>= 1) {
        s  += __shfl_xor_sync(0xffffffffu, s, off);
        s2 += __shfl_xor_sync(0xffffffffu, s2, off);
    }
    const int warp = t >> 5, lane = t & 31;
    if (lane == 0) { red[warp] = s; red[warp + 8] = s2; }
    __syncthreads();
    if (t < 32) {
        float a  = (lane < 8) ? red[lane] : 0.f;
        float b2 = (lane < 8) ? red[lane + 8] : 0.f;
#pragma unroll
        for (int off = 4; off > 0; off >>= 1) {
            a  += __shfl_xor_sync(0xffffffffu, a, off);
            b2 += __shfl_xor_sync(0xffffffffu, b2, off);
        }
        if (lane == 0) { red[0] = a; red[1] = b2; }
    }
    __syncthreads();
    const float mean = red[0] * (1.f / DM);
    const float var  = red[1] * (1.f / DM) - mean * mean;
    const float rstd = rsqrtf(var + 1e-5f);

    float4 g  = *(const float4*)&gamma[t * 4];
    float4 be = *(const float4*)&beta[t * 4];
    float4 o;
    o.x = (v0 - mean) * rstd * g.x + be.x;
    o.y = (v1 - mean) * rstd * g.y + be.y;
    o.z = (v2 - mean) * rstd * g.z + be.z;
    o.w = (v3 - mean) * rstd * g.w + be.w;
    *(float4*)&y[(size_t)row * DM + t * 4] = o;
}

// =========================================================================
extern "C" void kernel_launch(void* const* d_in, const int* in_sizes, int n_in,
                              void* d_out, int out_size)
{
    const float* query = (const float*)d_in[0];
    const float* key   = (const float*)d_in[1];
    const float* value = (const float*)d_in[2];
    const float* Wq    = (const float*)d_in[3];
    const float* bq    = (const float*)d_in[4];
    const float* Wk    = (const float*)d_in[5];
    const float* bk    = (const float*)d_in[6];
    const float* Wv    = (const float*)d_in[7];
    const float* bv    = (const float*)d_in[8];
    const float* Wfc   = (const float*)d_in[9];
    const float* bfc   = (const float*)d_in[10];
    const float* gamma = (const float*)d_in[11];
    const float* beta  = (const float*)d_in[12];

    float* y_out = (float*)d_out;
    float* attn_out = y_out + (size_t)L_SEQ * NB * DM;

    cudaFuncSetAttribute(attn_kernel,
                         cudaFuncAttributeMaxDynamicSharedMemorySize,
                         ATTN_SMEM_BYTES);
    cudaFuncSetAttribute(mma_gemm_kernel,
                         cudaFuncAttributeMaxDynamicSharedMemorySize,
                         GEMM_SMEM_BYTES);

    conv_w_kernel<<<dim3(DM / 32, DM / 32, 4), 256>>>(Wq, Wk, Wv, Wfc);
    conv_in_kernel<<<dim3(MROWS * DM / 2048, 3), 256>>>(query, key, value);

    mma_gemm_kernel<<<dim3(MROWS / 128, DM / 128, 3), 256, GEMM_SMEM_BYTES>>>(
        bq, bk, bv, bfc, 0);

    attn_kernel<<<dim3(L_SEQ / 128, HB), 256, ATTN_SMEM_BYTES>>>(attn_out);

    mma_gemm_kernel<<<dim3(MROWS / 128, DM / 128, 1), 256, GEMM_SMEM_BYTES>>>(
        bq, bk, bv, bfc, 1);

    ln_kernel<<<MROWS, 256>>>(query, gamma, beta, y_out);

    attn_norm_kernel<<<HB * L_SEQ, 256>>>(attn_out);
}

// round 7
// speedup vs baseline: 2.5268x; 1.1125x over previous
#include <cuda_runtime.h>
#include <cuda_bf16.h>
#include <math.h>
#include <float.h>
#include <stdint.h>

#define L_SEQ 2048
#define NB 2
#define DM 1024
#define NH 16
#define DHEAD 64
#define SPAN_W 128
#define MROWS (L_SEQ * NB)          // 4096
#define HB (NH * NB)                // 32

// ---------------- static scratch (no allocations allowed) ----------------
__device__ float g_fc[MROWS * DM];               // FC output (pre-LN)
__device__ float g_rowl[HB * L_SEQ];             // softmax row sum

// bf16 split operands
__device__ __nv_bfloat16 g_inhi[3][MROWS * DM];  // q/k/v inputs hi
__device__ __nv_bfloat16 g_inlo[3][MROWS * DM];  // lo
__device__ __nv_bfloat16 g_wthi[4][DM * DM];     // W^T [n][k] hi
__device__ __nv_bfloat16 g_wtlo[4][DM * DM];     // lo
__device__ __nv_bfloat16 g_aohi[MROWS * DM];     // attnout hi
__device__ __nv_bfloat16 g_aolo[MROWS * DM];     // attnout lo
// projected Q (x0.125) / K, head-major [hb][l][dk], bf16 hi/lo
__device__ __nv_bfloat16 g_qkhi[2][HB * L_SEQ * DHEAD];
__device__ __nv_bfloat16 g_qklo[2][HB * L_SEQ * DHEAD];
// projected V transposed [hb][dv][l], bf16 hi/lo
__device__ __nv_bfloat16 g_vthi[HB * DHEAD * L_SEQ];
__device__ __nv_bfloat16 g_vtlo[HB * DHEAD * L_SEQ];

// ---------------- helpers ----------------
__device__ __forceinline__ uint32_t smem_u32(const void* p) {
    uint32_t a;
    asm("{ .reg .u64 t; cvta.to.shared.u64 t, %1; cvt.u32.u64 %0, t; }"
        : "=r"(a) : "l"(p));
    return a;
}
__device__ __forceinline__ void ldsm4(uint32_t (&r)[4], uint32_t addr) {
    asm volatile("ldmatrix.sync.aligned.m8n8.x4.shared.b16 {%0,%1,%2,%3}, [%4];"
                 : "=r"(r[0]), "=r"(r[1]), "=r"(r[2]), "=r"(r[3]) : "r"(addr));
}
__device__ __forceinline__ void mma_bf16(float (&d)[4], const uint32_t (&a)[4],
                                         uint32_t b0, uint32_t b1) {
    asm volatile(
        "mma.sync.aligned.m16n8k16.row.col.f32.bf16.bf16.f32 "
        "{%0,%1,%2,%3}, {%4,%5,%6,%7}, {%8,%9}, {%0,%1,%2,%3};"
        : "+f"(d[0]), "+f"(d[1]), "+f"(d[2]), "+f"(d[3])
        : "r"(a[0]), "r"(a[1]), "r"(a[2]), "r"(a[3]), "r"(b0), "r"(b1));
}
#define CPA16(saddr, gptr) \
    asm volatile("cp.async.cg.shared.global [%0], [%1], 16;" \
                 :: "r"(saddr), "l"(__cvta_generic_to_global(gptr)) : "memory")
#define CPA_COMMIT() asm volatile("cp.async.commit_group;" ::: "memory")
#define CPA_WAIT0()  asm volatile("cp.async.wait_group 0;" ::: "memory")

// fast exp on FMA pipe, ~1e-7 rel (|x| < 80)
__device__ __forceinline__ float fexp(float x) {
    x = fmaxf(x, -80.f);
    float t = fmaf(x, 1.4426950408889634f, 12582912.f);
    float n = t - 12582912.f;
    float f = fmaf(n, -0.693145751953125f, x);
    f = fmaf(n, -1.428606765330187e-06f, f);
    float p = 1.3888889e-3f;
    p = fmaf(p, f, 8.3333338e-3f);
    p = fmaf(p, f, 4.1666668e-2f);
    p = fmaf(p, f, 1.6666667e-1f);
    p = fmaf(p, f, 5.0e-1f);
    p = fmaf(p, f, 1.0f);
    p = fmaf(p, f, 1.0f);
    int i = (int)n;
    return __int_as_float(__float_as_int(p) + (i << 23));
}
__device__ __forceinline__ uint32_t packbf(float a, float b) {
    __nv_bfloat162 t = __floats2bfloat162_rn(a, b);
    return *reinterpret_cast<uint32_t*>(&t);
}
// split pair into bf16 hi (packed) and bf16 lo (packed)
__device__ __forceinline__ void bsplit2(float a, float b, uint32_t& h, uint32_t& l) {
    __nv_bfloat16 ha = __float2bfloat16(a), hb = __float2bfloat16(b);
    __nv_bfloat162 hh = __halves2bfloat162(ha, hb);
    h = *reinterpret_cast<uint32_t*>(&hh);
    l = packbf(a - __bfloat162float(ha), b - __bfloat162float(hb));
}

// ======================== converter kernels ==============================
__global__ void __launch_bounds__(256)
conv_in_kernel(const float* __restrict__ q, const float* __restrict__ k,
               const float* __restrict__ v)
{
    const int z = blockIdx.y;
    const float* src = (z == 0) ? q : (z == 1) ? k : v;
    __nv_bfloat16* dhi = g_inhi[z];
    __nv_bfloat16* dlo = g_inlo[z];
    size_t base = ((size_t)blockIdx.x * 256 + threadIdx.x) * 8;
    float4 a = *(const float4*)(src + base);
    float4 b = *(const float4*)(src + base + 4);
    __nv_bfloat16 hi[8], lo[8];
    float xs[8] = {a.x, a.y, a.z, a.w, b.x, b.y, b.z, b.w};
#pragma unroll
    for (int i = 0; i < 8; i++) {
        hi[i] = __float2bfloat16(xs[i]);
        lo[i] = __float2bfloat16(xs[i] - __bfloat162float(hi[i]));
    }
    *(uint4*)(dhi + base) = *(uint4*)hi;
    *(uint4*)(dlo + base) = *(uint4*)lo;
}

__global__ void __launch_bounds__(256)
conv_w_kernel(const float* __restrict__ Wq, const float* __restrict__ Wk,
              const float* __restrict__ Wv, const float* __restrict__ Wfc)
{
    __shared__ float tile[32][33];
    const int z = blockIdx.z;
    const float* W = (z == 0) ? Wq : (z == 1) ? Wk : (z == 2) ? Wv : Wfc;
    __nv_bfloat16* dhi = g_wthi[z];
    __nv_bfloat16* dlo = g_wtlo[z];
    const int n0 = blockIdx.x * 32, k0 = blockIdx.y * 32;
    const int c = threadIdx.x & 31, r0 = (threadIdx.x >> 5) * 4;
#pragma unroll
    for (int rr = 0; rr < 4; rr++)
        tile[r0 + rr][c] = W[(size_t)(k0 + r0 + rr) * DM + n0 + c];
    __syncthreads();
#pragma unroll
    for (int rr = 0; rr < 4; rr++) {
        int n = n0 + r0 + rr;
        float x = tile[c][r0 + rr];
        __nv_bfloat16 hi = __float2bfloat16(x);
        __nv_bfloat16 lo = __float2bfloat16(x - __bfloat162float(hi));
        dhi[(size_t)n * DM + k0 + c] = hi;
        dlo[(size_t)n * DM + k0 + c] = lo;
    }
}

// ======================== split-bf16 HMMA GEMM (cp.async) ================
#define TSX 40
#define TILE_B (128 * TSX * 2)
#define GEMM_SMEM_BYTES (2 * 4 * TILE_B)   // 81920

__global__ void __launch_bounds__(256, 2)
mma_gemm_kernel(const float* __restrict__ bq, const float* __restrict__ bk,
                const float* __restrict__ bv, const float* __restrict__ bfc,
                int is_fc)
{
    extern __shared__ char dyn[];
    const uint32_t sb = smem_u32(dyn);
    const int tid = threadIdx.x, wid = tid >> 5, lane = tid & 31;
    const int m0 = blockIdx.x * 128, n0 = blockIdx.y * 128;
    const int z = blockIdx.z;

    const __nv_bfloat16 *Ah, *Al, *Bh, *Bl;
    const float* bias;
    if (is_fc) {
        Ah = g_aohi; Al = g_aolo; Bh = g_wthi[3]; Bl = g_wtlo[3]; bias = bfc;
    } else {
        Ah = g_inhi[z]; Al = g_inlo[z]; Bh = g_wthi[z]; Bl = g_wtlo[z];
        bias = (z == 0) ? bq : (z == 1) ? bk : bv;
    }
    const __nv_bfloat16* srcs[4] = {
        Ah + (size_t)m0 * DM, Al + (size_t)m0 * DM,
        Bh + (size_t)n0 * DM, Bl + (size_t)n0 * DM };

    const int wm = (wid & 3) * 32;
    const int wn = (wid >> 2) * 64;

    float acc[2][8][4];
#pragma unroll
    for (int ms = 0; ms < 2; ms++)
#pragma unroll
        for (int ns = 0; ns < 8; ns++)
#pragma unroll
            for (int c = 0; c < 4; c++) acc[ms][ns][c] = 0.f;

    const int r_ld = tid >> 2;
    const int c_ld = (tid & 3) * 8;

    auto issue_tile = [&](int buf, int k0) {
#pragma unroll
        for (int t = 0; t < 4; t++)
#pragma unroll
            for (int u = 0; u < 2; u++) {
                uint32_t sa = sb + buf * (4 * TILE_B) + t * TILE_B +
                              ((r_ld + u * 64) * TSX + c_ld) * 2;
                CPA16(sa, srcs[t] + (size_t)(r_ld + u * 64) * DM + k0 + c_ld);
            }
        CPA_COMMIT();
    };

    issue_tile(0, 0);
    CPA_WAIT0();
    __syncthreads();

    const int rowA = wm + (lane & 15);
    const int colA = (lane >> 4) << 3;
    const int rowB = wn + (lane & 7) + ((lane >> 4) << 3);
    const int colB = ((lane >> 3) & 1) << 3;

    for (int step = 0; step < 32; step++) {
        const int buf = step & 1;
        const uint32_t base = sb + buf * (4 * TILE_B);
        const int has_next = (step + 1 < 32);
        if (has_next) issue_tile(buf ^ 1, (step + 1) * 32);

#pragma unroll
        for (int kh = 0; kh < 32; kh += 16) {
            uint32_t ah[2][4], al[2][4];
#pragma unroll
            for (int ms = 0; ms < 2; ms++) {
                uint32_t off = ((rowA + ms * 16) * TSX + kh + colA) * 2;
                ldsm4(ah[ms], base + 0 * TILE_B + off);
                ldsm4(al[ms], base + 1 * TILE_B + off);
            }
            uint32_t bh[8][2], bl[8][2];
#pragma unroll
            for (int np = 0; np < 4; np++) {
                uint32_t off = ((rowB + np * 16) * TSX + kh + colB) * 2;
                uint32_t t4[4];
                ldsm4(t4, base + 2 * TILE_B + off);
                bh[2 * np][0] = t4[0]; bh[2 * np][1] = t4[1];
                bh[2 * np + 1][0] = t4[2]; bh[2 * np + 1][1] = t4[3];
                ldsm4(t4, base + 3 * TILE_B + off);
                bl[2 * np][0] = t4[0]; bl[2 * np][1] = t4[1];
                bl[2 * np + 1][0] = t4[2]; bl[2 * np + 1][1] = t4[3];
            }
#pragma unroll
            for (int ms = 0; ms < 2; ms++)
#pragma unroll
                for (int ns = 0; ns < 8; ns++) {
                    mma_bf16(acc[ms][ns], ah[ms], bh[ns][0], bh[ns][1]);
                    mma_bf16(acc[ms][ns], ah[ms], bl[ns][0], bl[ns][1]);
                    mma_bf16(acc[ms][ns], al[ms], bh[ns][0], bh[ns][1]);
                }
        }
        if (has_next) {
            CPA_WAIT0();
            __syncthreads();
        }
    }

    const int qrow = lane >> 2;
    const int qcol = (lane & 3) * 2;
    const float scale = (!is_fc && z == 0) ? 0.125f : 1.0f;
#pragma unroll
    for (int ms = 0; ms < 2; ms++) {
#pragma unroll
        for (int ns = 0; ns < 8; ns++) {
            const int ncol = n0 + wn + ns * 8 + qcol;
            const float b0 = bias[ncol], b1 = bias[ncol + 1];
#pragma unroll
            for (int half = 0; half < 2; half++) {
                const int m = m0 + wm + ms * 16 + qrow + half * 8;
                float x0 = (acc[ms][ns][2 * half] + b0) * scale;
                float x1 = (acc[ms][ns][2 * half + 1] + b1) * scale;
                if (is_fc) {
                    *(float2*)(g_fc + (size_t)m * DM + ncol) = make_float2(x0, x1);
                } else {
                    const int l = m >> 1, bb = m & 1;
                    const int h = ncol >> 6, dkb = ncol & 63;
                    __nv_bfloat16 h0 = __float2bfloat16(x0);
                    __nv_bfloat16 l0 = __float2bfloat16(x0 - __bfloat162float(h0));
                    __nv_bfloat16 h1 = __float2bfloat16(x1);
                    __nv_bfloat16 l1 = __float2bfloat16(x1 - __bfloat162float(h1));
                    if (z < 2) {
                        size_t idx = ((size_t)(h * NB + bb) * L_SEQ + l) * DHEAD + dkb;
                        __nv_bfloat162 ph = __halves2bfloat162(h0, h1);
                        __nv_bfloat162 pl = __halves2bfloat162(l0, l1);
                        *(uint32_t*)(g_qkhi[z] + idx) = *(uint32_t*)&ph;
                        *(uint32_t*)(g_qklo[z] + idx) = *(uint32_t*)&pl;
                    } else {
                        size_t base2 = ((size_t)(h * NB + bb) * DHEAD + dkb) * L_SEQ + l;
                        g_vthi[base2] = h0;          g_vtlo[base2] = l0;
                        g_vthi[base2 + L_SEQ] = h1;  g_vtlo[base2 + L_SEQ] = l1;
                    }
                }
            }
        }
    }
}

// =========================================================================
// HMMA banded attention, SINGLE PASS (no max: softmax shift-invariance),
// P kept in registers (accumulator layout == A-fragment layout).
// smem 106KB -> 2 CTAs/SM.  8 warps x 16 rows; j processed in 64-col halves.
// =========================================================================
#define QKS 72           // Q/K smem row stride (bf16)
#define VTS 136          // Vt smem row stride
#define OFF_QH 0
#define OFF_QL 18432
#define OFF_KH 36864
#define OFF_KL 55296
#define OFF_VH 73728
#define OFF_VL 91136
#define ATTN_SMEM_BYTES 108544

__global__ void __launch_bounds__(256, 2)
attn_kernel(float* __restrict__ attn_raw)
{
    extern __shared__ char dyn[];
    const uint32_t sb = smem_u32(dyn);
    const int tid = threadIdx.x, wid = tid >> 5, lane = tid & 31;
    const int w16 = wid * 16;
    const int i0 = blockIdx.x * 128;
    const int hb = blockIdx.y;

    const __nv_bfloat16* Qh = g_qkhi[0] + (size_t)hb * L_SEQ * DHEAD;
    const __nv_bfloat16* Ql = g_qklo[0] + (size_t)hb * L_SEQ * DHEAD;
    const __nv_bfloat16* Kh = g_qkhi[1] + (size_t)hb * L_SEQ * DHEAD;
    const __nv_bfloat16* Kl = g_qklo[1] + (size_t)hb * L_SEQ * DHEAD;
    const __nv_bfloat16* Vh = g_vthi + (size_t)hb * DHEAD * L_SEQ;
    const __nv_bfloat16* Vl = g_vtlo + (size_t)hb * DHEAD * L_SEQ;
    float* rawbase = attn_raw + (size_t)hb * L_SEQ * L_SEQ;

    // load Q tile (persistent)
    {
        const __nv_bfloat16* src = Qh + (size_t)i0 * DHEAD;
        const __nv_bfloat16* srl = Ql + (size_t)i0 * DHEAD;
#pragma unroll
        for (int u = 0; u < 4; u++) {
            int idx = tid + u * 256;
            int r = idx >> 3, c = idx & 7;
            *(uint4*)(dyn + OFF_QH + (r * QKS + c * 8) * 2) =
                *(const uint4*)(src + (size_t)r * DHEAD + c * 8);
            *(uint4*)(dyn + OFF_QL + (r * QKS + c * 8) * 2) =
                *(const uint4*)(srl + (size_t)r * DHEAD + c * 8);
        }
    }

    const int ir0 = i0 + w16 + (lane >> 2);
    const int ir1 = ir0 + 8;
    const int jco = 2 * (lane & 3);

    const uint32_t qoff = ((w16 + (lane & 15)) * QKS + ((lane >> 4) << 3)) * 2;
    const uint32_t brow = (lane & 7) + ((lane >> 4) << 3);
    const uint32_t bcol = ((lane >> 3) & 1) << 3;

    float O[8][4];
#pragma unroll
    for (int n = 0; n < 8; n++)
#pragma unroll
        for (int e = 0; e < 4; e++) O[n][e] = 0.f;
    float sum0 = 0.f, sum1 = 0.f;

    for (int cch = 0; cch < 3; cch++) {
        int j0 = i0 + (cch - 1) * 128;
        if (j0 < 0 || j0 >= L_SEQ) continue;
        __syncthreads();     // prev chunk K/V fully consumed
        {
#pragma unroll
            for (int u = 0; u < 4; u++) {
                int idx = tid + u * 256;
                int r = idx >> 3, c = idx & 7;
                *(uint4*)(dyn + OFF_KH + (r * QKS + c * 8) * 2) =
                    *(const uint4*)(Kh + (size_t)(j0 + r) * DHEAD + c * 8);
                *(uint4*)(dyn + OFF_KL + (r * QKS + c * 8) * 2) =
                    *(const uint4*)(Kl + (size_t)(j0 + r) * DHEAD + c * 8);
            }
#pragma unroll
            for (int u = 0; u < 4; u++) {
                int idx = tid + u * 256;
                int r = idx >> 4, c = idx & 15;
                *(uint4*)(dyn + OFF_VH + (r * VTS + c * 8) * 2) =
                    *(const uint4*)(Vh + (size_t)r * L_SEQ + j0 + c * 8);
                *(uint4*)(dyn + OFF_VL + (r * VTS + c * 8) * 2) =
                    *(const uint4*)(Vl + (size_t)r * L_SEQ + j0 + c * 8);
            }
        }
        __syncthreads();

#pragma unroll
        for (int half = 0; half < 2; half++) {
            // ---- S = Q K^T for j in [j0+64*half, +64) ----
            float Sv[8][4];
#pragma unroll
            for (int n = 0; n < 8; n++)
#pragma unroll
                for (int e = 0; e < 4; e++) Sv[n][e] = 0.f;
#pragma unroll
            for (int ks = 0; ks < 4; ks++) {
                uint32_t ah[4], al[4];
                ldsm4(ah, sb + OFF_QH + qoff + ks * 32);
                ldsm4(al, sb + OFF_QL + qoff + ks * 32);
#pragma unroll
                for (int n2 = 0; n2 < 4; n2++) {
                    uint32_t off = ((half * 64 + n2 * 16 + brow) * QKS + ks * 16 + bcol) * 2;
                    uint32_t kh4[4], kl4[4];
                    ldsm4(kh4, sb + OFF_KH + off);
                    ldsm4(kl4, sb + OFF_KL + off);
                    mma_bf16(Sv[2 * n2], ah, kh4[0], kh4[1]);
                    mma_bf16(Sv[2 * n2], ah, kl4[0], kl4[1]);
                    mma_bf16(Sv[2 * n2], al, kh4[0], kh4[1]);
                    mma_bf16(Sv[2 * n2 + 1], ah, kh4[2], kh4[3]);
                    mma_bf16(Sv[2 * n2 + 1], ah, kl4[2], kl4[3]);
                    mma_bf16(Sv[2 * n2 + 1], al, kh4[2], kh4[3]);
                }
            }

            // ---- mask + exp (m=0) + gmem p + row sums ----
#pragma unroll
            for (int n = 0; n < 8; n++) {
                int j = j0 + half * 64 + n * 8 + jco;
                int d0 = ir0 - j, d1 = ir1 - j;
                float p00 = (d0 >= -SPAN_W && d0 <= SPAN_W) ? fexp(Sv[n][0]) : 0.f;
                float p01 = (d0 - 1 >= -SPAN_W && d0 - 1 <= SPAN_W) ? fexp(Sv[n][1]) : 0.f;
                float p10 = (d1 >= -SPAN_W && d1 <= SPAN_W) ? fexp(Sv[n][2]) : 0.f;
                float p11 = (d1 - 1 >= -SPAN_W && d1 - 1 <= SPAN_W) ? fexp(Sv[n][3]) : 0.f;
                sum0 += p00 + p01;
                sum1 += p10 + p11;
                *(float2*)(rawbase + (size_t)ir0 * L_SEQ + j) = make_float2(p00, p01);
                *(float2*)(rawbase + (size_t)ir1 * L_SEQ + j) = make_float2(p10, p11);
                Sv[n][0] = p00; Sv[n][1] = p01; Sv[n][2] = p10; Sv[n][3] = p11;
            }

            // ---- O += P V : P A-fragments straight from registers ----
#pragma unroll
            for (int t = 0; t < 4; t++) {
                uint32_t afh[4], afl[4];
                bsplit2(Sv[2 * t][0], Sv[2 * t][1], afh[0], afl[0]);
                bsplit2(Sv[2 * t][2], Sv[2 * t][3], afh[1], afl[1]);
                bsplit2(Sv[2 * t + 1][0], Sv[2 * t + 1][1], afh[2], afl[2]);
                bsplit2(Sv[2 * t + 1][2], Sv[2 * t + 1][3], afh[3], afl[3]);
#pragma unroll
                for (int n2 = 0; n2 < 4; n2++) {
                    uint32_t off = ((n2 * 16 + brow) * VTS + half * 64 + t * 16 + bcol) * 2;
                    uint32_t vh4[4], vl4[4];
                    ldsm4(vh4, sb + OFF_VH + off);
                    ldsm4(vl4, sb + OFF_VL + off);
                    mma_bf16(O[2 * n2], afh, vh4[0], vh4[1]);
                    mma_bf16(O[2 * n2], afl, vh4[0], vh4[1]);
                    mma_bf16(O[2 * n2], afh, vl4[0], vl4[1]);
                    mma_bf16(O[2 * n2 + 1], afh, vh4[2], vh4[3]);
                    mma_bf16(O[2 * n2 + 1], afl, vh4[2], vh4[3]);
                    mma_bf16(O[2 * n2 + 1], afh, vl4[2], vl4[3]);
                }
            }
        }
    }

    sum0 += __shfl_xor_sync(0xffffffffu, sum0, 1);
    sum0 += __shfl_xor_sync(0xffffffffu, sum0, 2);
    sum1 += __shfl_xor_sync(0xffffffffu, sum1, 1);
    sum1 += __shfl_xor_sync(0xffffffffu, sum1, 2);
    const float inv0 = 1.f / sum0;
    const float inv1 = 1.f / sum1;
    if ((lane & 3) == 0) {
        g_rowl[hb * L_SEQ + ir0] = sum0;
        g_rowl[hb * L_SEQ + ir1] = sum1;
    }

    // epilogue: attnout bf16 hi/lo  [l b][h dv]
    const int h = hb >> 1, bb = hb & 1;
#pragma unroll
    for (int n = 0; n < 8; n++) {
        int dv = n * 8 + jco;
        float x0 = O[n][0] * inv0, x1 = O[n][1] * inv0;
        float y0 = O[n][2] * inv1, y1 = O[n][3] * inv1;
        uint32_t h0, l0, h1, l1;
        bsplit2(x0, x1, h0, l0);
        bsplit2(y0, y1, h1, l1);
        size_t i0x = ((size_t)ir0 * NB + bb) * DM + h * DHEAD + dv;
        size_t i1x = ((size_t)ir1 * NB + bb) * DM + h * DHEAD + dv;
        *(uint32_t*)(g_aohi + i0x) = h0;
        *(uint32_t*)(g_aolo + i0x) = l0;
        *(uint32_t*)(g_aohi + i1x) = h1;
        *(uint32_t*)(g_aolo + i1x) = l1;
    }
}

// =========================================================================
// Normalize: p (unnormalized exp) * inv in band; zero elsewhere.
// =========================================================================
__global__ void __launch_bounds__(256)
attn_norm_kernel(float* __restrict__ attn)
{
    const int row = blockIdx.x;
    const int i = row & (L_SEQ - 1);
    const float inv = 1.f / g_rowl[row];
    float* p = attn + (size_t)row * L_SEQ;
    const int j0 = threadIdx.x * 8;
    float out[8];
#pragma unroll
    for (int u = 0; u < 8; u++) {
        int j = j0 + u;
        int d = i - j;
        bool inband = (d >= -SPAN_W && d <= SPAN_W);
        out[u] = inband ? p[j] * inv : 0.f;
    }
    *(float4*)&p[j0]     = make_float4(out[0], out[1], out[2], out[3]);
    *(float4*)&p[j0 + 4] = make_float4(out[4], out[5], out[6], out[7]);
}

// =========================================================================
// Residual + LayerNorm.
// =========================================================================
__global__ void __launch_bounds__(256)
ln_kernel(const float* __restrict__ query, const float* __restrict__ gamma,
          const float* __restrict__ beta, float* __restrict__ y)
{
    __shared__ float red[16];
    const int row = blockIdx.x;
    const int t = threadIdx.x;

    float4 f = *(const float4*)&g_fc[(size_t)row * DM + t * 4];
    float4 q = *(const float4*)&query[(size_t)row * DM + t * 4];
    float v0 = f.x + q.x, v1 = f.y + q.y, v2 = f.z + q.z, v3 = f.w + q.w;

    float s = v0 + v1 + v2 + v3;
    float s2 = v0 * v0 + v1 * v1 + v2 * v2 + v3 * v3;
#pragma unroll
    for (int off = 16; off > 0; off >>= 1) {
        s  += __shfl_xor_sync(0xffffffffu, s, off);
        s2 += __shfl_xor_sync(0xffffffffu, s2, off);
    }
    const int warp = t >> 5, lane = t & 31;
    if (lane == 0) { red[warp] = s; red[warp + 8] = s2; }
    __syncthreads();
    if (t < 32) {
        float a  = (lane < 8) ? red[lane] : 0.f;
        float b2 = (lane < 8) ? red[lane + 8] : 0.f;
#pragma unroll
        for (int off = 4; off > 0; off >>= 1) {
            a  += __shfl_xor_sync(0xffffffffu, a, off);
            b2 += __shfl_xor_sync(0xffffffffu, b2, off);
        }
        if (lane == 0) { red[0] = a; red[1] = b2; }
    }
    __syncthreads();
    const float mean = red[0] * (1.f / DM);
    const float var  = red[1] * (1.f / DM) - mean * mean;
    const float rstd = rsqrtf(var + 1e-5f);

    float4 g  = *(const float4*)&gamma[t * 4];
    float4 be = *(const float4*)&beta[t * 4];
    float4 o;
    o.x = (v0 - mean) * rstd * g.x + be.x;
    o.y = (v1 - mean) * rstd * g.y + be.y;
    o.z = (v2 - mean) * rstd * g.z + be.z;
    o.w = (v3 - mean) * rstd * g.w + be.w;
    *(float4*)&y[(size_t)row * DM + t * 4] = o;
}

// =========================================================================
extern "C" void kernel_launch(void* const* d_in, const int* in_sizes, int n_in,
                              void* d_out, int out_size)
{
    const float* query = (const float*)d_in[0];
    const float* key   = (const float*)d_in[1];
    const float* value = (const float*)d_in[2];
    const float* Wq    = (const float*)d_in[3];
    const float* bq    = (const float*)d_in[4];
    const float* Wk    = (const float*)d_in[5];
    const float* bk    = (const float*)d_in[6];
    const float* Wv    = (const float*)d_in[7];
    const float* bv    = (const float*)d_in[8];
    const float* Wfc   = (const float*)d_in[9];
    const float* bfc   = (const float*)d_in[10];
    const float* gamma = (const float*)d_in[11];
    const float* beta  = (const float*)d_in[12];

    float* y_out = (float*)d_out;
    float* attn_out = y_out + (size_t)L_SEQ * NB * DM;

    cudaFuncSetAttribute(attn_kernel,
                         cudaFuncAttributeMaxDynamicSharedMemorySize,
                         ATTN_SMEM_BYTES);
    cudaFuncSetAttribute(mma_gemm_kernel,
                         cudaFuncAttributeMaxDynamicSharedMemorySize,
                         GEMM_SMEM_BYTES);

    conv_w_kernel<<<dim3(DM / 32, DM / 32, 4), 256>>>(Wq, Wk, Wv, Wfc);
    conv_in_kernel<<<dim3(MROWS * DM / 2048, 3), 256>>>(query, key, value);

    mma_gemm_kernel<<<dim3(MROWS / 128, DM / 128, 3), 256, GEMM_SMEM_BYTES>>>(
        bq, bk, bv, bfc, 0);

    attn_kernel<<<dim3(L_SEQ / 128, HB), 256, ATTN_SMEM_BYTES>>>(attn_out);

    mma_gemm_kernel<<<dim3(MROWS / 128, DM / 128, 1), 256, GEMM_SMEM_BYTES>>>(
        bq, bk, bv, bfc, 1);

    ln_kernel<<<MROWS, 256>>>(query, gamma, beta, y_out);

    attn_norm_kernel<<<HB * L_SEQ, 256>>>(attn_out);
}

// round 8
// speedup vs baseline: 3.3890x; 1.3413x over previous
#include <cuda_runtime.h>
#include <cuda_fp16.h>
#include <math.h>
#include <float.h>
#include <stdint.h>

#define L_SEQ 2048
#define NB 2
#define DM 1024
#define NH 16
#define DHEAD 64
#define SPAN_W 128
#define MROWS (L_SEQ * NB)          // 4096
#define HB (NH * NB)                // 32

// ---------------- static scratch (no allocations allowed) ----------------
__device__ float g_fc[MROWS * DM];               // FC output (pre-LN)
__device__ float g_rowl[HB * L_SEQ];             // softmax row sum

// fp16 split operands: A-side split hi/lo (exact), B-side single-rounded.
__device__ __half g_inhi[3][MROWS * DM];         // q/k/v inputs hi
__device__ __half g_inlo[3][MROWS * DM];         // lo
__device__ __half g_wth[4][DM * DM];             // W^T [n][k] (single fp16)
__device__ __half g_aohi[MROWS * DM];            // attnout hi
__device__ __half g_aolo[MROWS * DM];            // attnout lo
// projected Q (x0.125) hi/lo + K single, head-major [hb][l][dk]
__device__ __half g_qh[HB * L_SEQ * DHEAD];
__device__ __half g_ql[HB * L_SEQ * DHEAD];
__device__ __half g_kh[HB * L_SEQ * DHEAD];
// projected V transposed [hb][dv][l], single fp16
__device__ __half g_vth[HB * DHEAD * L_SEQ];

// ---------------- helpers ----------------
__device__ __forceinline__ uint32_t smem_u32(const void* p) {
    uint32_t a;
    asm("{ .reg .u64 t; cvta.to.shared.u64 t, %1; cvt.u32.u64 %0, t; }"
        : "=r"(a) : "l"(p));
    return a;
}
__device__ __forceinline__ void ldsm4(uint32_t (&r)[4], uint32_t addr) {
    asm volatile("ldmatrix.sync.aligned.m8n8.x4.shared.b16 {%0,%1,%2,%3}, [%4];"
                 : "=r"(r[0]), "=r"(r[1]), "=r"(r[2]), "=r"(r[3]) : "r"(addr));
}
__device__ __forceinline__ void mma_f16(float (&d)[4], const uint32_t (&a)[4],
                                        uint32_t b0, uint32_t b1) {
    asm volatile(
        "mma.sync.aligned.m16n8k16.row.col.f32.f16.f16.f32 "
        "{%0,%1,%2,%3}, {%4,%5,%6,%7}, {%8,%9}, {%0,%1,%2,%3};"
        : "+f"(d[0]), "+f"(d[1]), "+f"(d[2]), "+f"(d[3])
        : "r"(a[0]), "r"(a[1]), "r"(a[2]), "r"(a[3]), "r"(b0), "r"(b1));
}
#define CPA16(saddr, gptr) \
    asm volatile("cp.async.cg.shared.global [%0], [%1], 16;" \
                 :: "r"(saddr), "l"(__cvta_generic_to_global(gptr)) : "memory")
#define CPA_COMMIT() asm volatile("cp.async.commit_group;" ::: "memory")
#define CPA_WAIT0()  asm volatile("cp.async.wait_group 0;" ::: "memory")

// fast exp on FMA pipe, ~1e-7 rel (|x| < 80)
__device__ __forceinline__ float fexp(float x) {
    x = fmaxf(x, -80.f);
    float t = fmaf(x, 1.4426950408889634f, 12582912.f);
    float n = t - 12582912.f;
    float f = fmaf(n, -0.693145751953125f, x);
    f = fmaf(n, -1.428606765330187e-06f, f);
    float p = 1.3888889e-3f;
    p = fmaf(p, f, 8.3333338e-3f);
    p = fmaf(p, f, 4.1666668e-2f);
    p = fmaf(p, f, 1.6666667e-1f);
    p = fmaf(p, f, 5.0e-1f);
    p = fmaf(p, f, 1.0f);
    p = fmaf(p, f, 1.0f);
    int i = (int)n;
    return __int_as_float(__float_as_int(p) + (i << 23));
}
__device__ __forceinline__ uint32_t packh2(float a, float b) {
    __half2 t = __floats2half2_rn(a, b);
    return *reinterpret_cast<uint32_t*>(&t);
}
__device__ __forceinline__ void hsplit2(float a, float b, uint32_t& h, uint32_t& l) {
    __half ha = __float2half_rn(a), hb = __float2half_rn(b);
    __half2 hh = __halves2half2(ha, hb);
    h = *reinterpret_cast<uint32_t*>(&hh);
    l = packh2(a - __half2float(ha), b - __half2float(hb));
}

// ======================== converter kernels ==============================
__global__ void __launch_bounds__(256)
conv_in_kernel(const float* __restrict__ q, const float* __restrict__ k,
               const float* __restrict__ v)
{
    const int z = blockIdx.y;
    const float* src = (z == 0) ? q : (z == 1) ? k : v;
    __half* dhi = g_inhi[z];
    __half* dlo = g_inlo[z];
    size_t base = ((size_t)blockIdx.x * 256 + threadIdx.x) * 8;
    float4 a = *(const float4*)(src + base);
    float4 b = *(const float4*)(src + base + 4);
    __half hi[8], lo[8];
    float xs[8] = {a.x, a.y, a.z, a.w, b.x, b.y, b.z, b.w};
#pragma unroll
    for (int i = 0; i < 8; i++) {
        hi[i] = __float2half_rn(xs[i]);
        lo[i] = __float2half_rn(xs[i] - __half2float(hi[i]));
    }
    *(uint4*)(dhi + base) = *(uint4*)hi;
    *(uint4*)(dlo + base) = *(uint4*)lo;
}

__global__ void __launch_bounds__(256)
conv_w_kernel(const float* __restrict__ Wq, const float* __restrict__ Wk,
              const float* __restrict__ Wv, const float* __restrict__ Wfc)
{
    __shared__ float tile[32][33];
    const int z = blockIdx.z;
    const float* W = (z == 0) ? Wq : (z == 1) ? Wk : (z == 2) ? Wv : Wfc;
    __half* dh = g_wth[z];
    const int n0 = blockIdx.x * 32, k0 = blockIdx.y * 32;
    const int c = threadIdx.x & 31, r0 = (threadIdx.x >> 5) * 4;
#pragma unroll
    for (int rr = 0; rr < 4; rr++)
        tile[r0 + rr][c] = W[(size_t)(k0 + r0 + rr) * DM + n0 + c];
    __syncthreads();
#pragma unroll
    for (int rr = 0; rr < 4; rr++) {
        int n = n0 + r0 + rr;
        dh[(size_t)n * DM + k0 + c] = __float2half_rn(tile[c][r0 + rr]);
    }
}

// ======================== fp16 2-term HMMA GEMM (cp.async) ===============
// D = (Ah + Al) @ Bh,  A split exact, B single-rounded fp16.
#define TSX 40
#define TILE_B (128 * TSX * 2)
#define GEMM_SMEM_BYTES (2 * 3 * TILE_B)   // 61440

__global__ void __launch_bounds__(256, 2)
mma_gemm_kernel(const float* __restrict__ bq, const float* __restrict__ bk,
                const float* __restrict__ bv, const float* __restrict__ bfc,
                int is_fc)
{
    extern __shared__ char dyn[];
    const uint32_t sb = smem_u32(dyn);
    const int tid = threadIdx.x, wid = tid >> 5, lane = tid & 31;
    const int m0 = blockIdx.x * 128, n0 = blockIdx.y * 128;
    const int z = blockIdx.z;

    const __half *Ah, *Al, *Bh;
    const float* bias;
    if (is_fc) {
        Ah = g_aohi; Al = g_aolo; Bh = g_wth[3]; bias = bfc;
    } else {
        Ah = g_inhi[z]; Al = g_inlo[z]; Bh = g_wth[z];
        bias = (z == 0) ? bq : (z == 1) ? bk : bv;
    }
    const __half* srcs[3] = {
        Ah + (size_t)m0 * DM, Al + (size_t)m0 * DM, Bh + (size_t)n0 * DM };

    const int wm = (wid & 3) * 32;
    const int wn = (wid >> 2) * 64;

    float acc[2][8][4];
#pragma unroll
    for (int ms = 0; ms < 2; ms++)
#pragma unroll
        for (int ns = 0; ns < 8; ns++)
#pragma unroll
            for (int c = 0; c < 4; c++) acc[ms][ns][c] = 0.f;

    const int r_ld = tid >> 2;
    const int c_ld = (tid & 3) * 8;

    auto issue_tile = [&](int buf, int k0) {
#pragma unroll
        for (int t = 0; t < 3; t++)
#pragma unroll
            for (int u = 0; u < 2; u++) {
                uint32_t sa = sb + buf * (3 * TILE_B) + t * TILE_B +
                              ((r_ld + u * 64) * TSX + c_ld) * 2;
                CPA16(sa, srcs[t] + (size_t)(r_ld + u * 64) * DM + k0 + c_ld);
            }
        CPA_COMMIT();
    };

    issue_tile(0, 0);
    CPA_WAIT0();
    __syncthreads();

    const int rowA = wm + (lane & 15);
    const int colA = (lane >> 4) << 3;
    const int rowB = wn + (lane & 7) + ((lane >> 4) << 3);
    const int colB = ((lane >> 3) & 1) << 3;

    for (int step = 0; step < 32; step++) {
        const int buf = step & 1;
        const uint32_t base = sb + buf * (3 * TILE_B);
        const int has_next = (step + 1 < 32);
        if (has_next) issue_tile(buf ^ 1, (step + 1) * 32);

#pragma unroll
        for (int kh = 0; kh < 32; kh += 16) {
            uint32_t ah[2][4], al[2][4];
#pragma unroll
            for (int ms = 0; ms < 2; ms++) {
                uint32_t off = ((rowA + ms * 16) * TSX + kh + colA) * 2;
                ldsm4(ah[ms], base + 0 * TILE_B + off);
                ldsm4(al[ms], base + 1 * TILE_B + off);
            }
            uint32_t bh[8][2];
#pragma unroll
            for (int np = 0; np < 4; np++) {
                uint32_t off = ((rowB + np * 16) * TSX + kh + colB) * 2;
                uint32_t t4[4];
                ldsm4(t4, base + 2 * TILE_B + off);
                bh[2 * np][0] = t4[0]; bh[2 * np][1] = t4[1];
                bh[2 * np + 1][0] = t4[2]; bh[2 * np + 1][1] = t4[3];
            }
#pragma unroll
            for (int ms = 0; ms < 2; ms++)
#pragma unroll
                for (int ns = 0; ns < 8; ns++) {
                    mma_f16(acc[ms][ns], ah[ms], bh[ns][0], bh[ns][1]);
                    mma_f16(acc[ms][ns], al[ms], bh[ns][0], bh[ns][1]);
                }
        }
        if (has_next) {
            CPA_WAIT0();
            __syncthreads();
        }
    }

    const int qrow = lane >> 2;
    const int qcol = (lane & 3) * 2;
    const float scale = (!is_fc && z == 0) ? 0.125f : 1.0f;
#pragma unroll
    for (int ms = 0; ms < 2; ms++) {
#pragma unroll
        for (int ns = 0; ns < 8; ns++) {
            const int ncol = n0 + wn + ns * 8 + qcol;
            const float b0 = bias[ncol], b1 = bias[ncol + 1];
#pragma unroll
            for (int half = 0; half < 2; half++) {
                const int m = m0 + wm + ms * 16 + qrow + half * 8;
                float x0 = (acc[ms][ns][2 * half] + b0) * scale;
                float x1 = (acc[ms][ns][2 * half + 1] + b1) * scale;
                if (is_fc) {
                    *(float2*)(g_fc + (size_t)m * DM + ncol) = make_float2(x0, x1);
                } else {
                    const int l = m >> 1, bb = m & 1;
                    const int h = ncol >> 6, dkb = ncol & 63;
                    if (z == 0) {
                        size_t idx = ((size_t)(h * NB + bb) * L_SEQ + l) * DHEAD + dkb;
                        uint32_t ph, pl;
                        hsplit2(x0, x1, ph, pl);
                        *(uint32_t*)(g_qh + idx) = ph;
                        *(uint32_t*)(g_ql + idx) = pl;
                    } else if (z == 1) {
                        size_t idx = ((size_t)(h * NB + bb) * L_SEQ + l) * DHEAD + dkb;
                        *(uint32_t*)(g_kh + idx) = packh2(x0, x1);
                    } else {
                        size_t base2 = ((size_t)(h * NB + bb) * DHEAD + dkb) * L_SEQ + l;
                        g_vth[base2] = __float2half_rn(x0);
                        g_vth[base2 + L_SEQ] = __float2half_rn(x1);
                    }
                }
            }
        }
    }
}

// =========================================================================
// fp16 HMMA banded attention, single pass, P in registers.
// S = (Qh+Ql) Kh^T ;  O = (Ph+Pl) Vh.  smem 71KB -> 2 CTAs/SM.
// =========================================================================
#define QKS 72           // Q/K smem row stride (halves)
#define VTS 136          // Vt smem row stride
#define OFF_QH 0
#define OFF_QL 18432
#define OFF_KH 36864
#define OFF_VH 55296
#define ATTN_SMEM_BYTES (55296 + 64 * VTS * 2)   // 72704

__global__ void __launch_bounds__(256, 2)
attn_kernel(float* __restrict__ attn_raw)
{
    extern __shared__ char dyn[];
    const uint32_t sb = smem_u32(dyn);
    const int tid = threadIdx.x, wid = tid >> 5, lane = tid & 31;
    const int w16 = wid * 16;
    const int i0 = blockIdx.x * 128;
    const int hb = blockIdx.y;

    const __half* Qh = g_qh + (size_t)hb * L_SEQ * DHEAD;
    const __half* Ql = g_ql + (size_t)hb * L_SEQ * DHEAD;
    const __half* Kh = g_kh + (size_t)hb * L_SEQ * DHEAD;
    const __half* Vh = g_vth + (size_t)hb * DHEAD * L_SEQ;
    float* rawbase = attn_raw + (size_t)hb * L_SEQ * L_SEQ;

    // load Q tile (persistent)
    {
        const __half* src = Qh + (size_t)i0 * DHEAD;
        const __half* srl = Ql + (size_t)i0 * DHEAD;
#pragma unroll
        for (int u = 0; u < 4; u++) {
            int idx = tid + u * 256;
            int r = idx >> 3, c = idx & 7;
            *(uint4*)(dyn + OFF_QH + (r * QKS + c * 8) * 2) =
                *(const uint4*)(src + (size_t)r * DHEAD + c * 8);
            *(uint4*)(dyn + OFF_QL + (r * QKS + c * 8) * 2) =
                *(const uint4*)(srl + (size_t)r * DHEAD + c * 8);
        }
    }

    const int ir0 = i0 + w16 + (lane >> 2);
    const int ir1 = ir0 + 8;
    const int jco = 2 * (lane & 3);

    const uint32_t qoff = ((w16 + (lane & 15)) * QKS + ((lane >> 4) << 3)) * 2;
    const uint32_t brow = (lane & 7) + ((lane >> 4) << 3);
    const uint32_t bcol = ((lane >> 3) & 1) << 3;

    float O[8][4];
#pragma unroll
    for (int n = 0; n < 8; n++)
#pragma unroll
        for (int e = 0; e < 4; e++) O[n][e] = 0.f;
    float sum0 = 0.f, sum1 = 0.f;

    for (int cch = 0; cch < 3; cch++) {
        int j0 = i0 + (cch - 1) * 128;
        if (j0 < 0 || j0 >= L_SEQ) continue;
        __syncthreads();     // prev chunk K/V fully consumed
        {
#pragma unroll
            for (int u = 0; u < 4; u++) {
                int idx = tid + u * 256;
                int r = idx >> 3, c = idx & 7;
                *(uint4*)(dyn + OFF_KH + (r * QKS + c * 8) * 2) =
                    *(const uint4*)(Kh + (size_t)(j0 + r) * DHEAD + c * 8);
            }
#pragma unroll
            for (int u = 0; u < 4; u++) {
                int idx = tid + u * 256;
                int r = idx >> 4, c = idx & 15;
                *(uint4*)(dyn + OFF_VH + (r * VTS + c * 8) * 2) =
                    *(const uint4*)(Vh + (size_t)r * L_SEQ + j0 + c * 8);
            }
        }
        __syncthreads();

#pragma unroll
        for (int half = 0; half < 2; half++) {
            // ---- S = Q K^T for 64 j-cols ----
            float Sv[8][4];
#pragma unroll
            for (int n = 0; n < 8; n++)
#pragma unroll
                for (int e = 0; e < 4; e++) Sv[n][e] = 0.f;
#pragma unroll
            for (int ks = 0; ks < 4; ks++) {
                uint32_t ah[4], al[4];
                ldsm4(ah, sb + OFF_QH + qoff + ks * 32);
                ldsm4(al, sb + OFF_QL + qoff + ks * 32);
#pragma unroll
                for (int n2 = 0; n2 < 4; n2++) {
                    uint32_t off = ((half * 64 + n2 * 16 + brow) * QKS + ks * 16 + bcol) * 2;
                    uint32_t kh4[4];
                    ldsm4(kh4, sb + OFF_KH + off);
                    mma_f16(Sv[2 * n2], ah, kh4[0], kh4[1]);
                    mma_f16(Sv[2 * n2], al, kh4[0], kh4[1]);
                    mma_f16(Sv[2 * n2 + 1], ah, kh4[2], kh4[3]);
                    mma_f16(Sv[2 * n2 + 1], al, kh4[2], kh4[3]);
                }
            }

            // ---- mask + exp (m=0) + gmem p + row sums ----
#pragma unroll
            for (int n = 0; n < 8; n++) {
                int j = j0 + half * 64 + n * 8 + jco;
                int d0 = ir0 - j, d1 = ir1 - j;
                float p00 = (d0 >= -SPAN_W && d0 <= SPAN_W) ? fexp(Sv[n][0]) : 0.f;
                float p01 = (d0 - 1 >= -SPAN_W && d0 - 1 <= SPAN_W) ? fexp(Sv[n][1]) : 0.f;
                float p10 = (d1 >= -SPAN_W && d1 <= SPAN_W) ? fexp(Sv[n][2]) : 0.f;
                float p11 = (d1 - 1 >= -SPAN_W && d1 - 1 <= SPAN_W) ? fexp(Sv[n][3]) : 0.f;
                sum0 += p00 + p01;
                sum1 += p10 + p11;
                *(float2*)(rawbase + (size_t)ir0 * L_SEQ + j) = make_float2(p00, p01);
                *(float2*)(rawbase + (size_t)ir1 * L_SEQ + j) = make_float2(p10, p11);
                Sv[n][0] = p00; Sv[n][1] = p01; Sv[n][2] = p10; Sv[n][3] = p11;
            }

            // ---- O += P V (P A-fragments from registers) ----
#pragma unroll
            for (int t = 0; t < 4; t++) {
                uint32_t afh[4], afl[4];
                hsplit2(Sv[2 * t][0], Sv[2 * t][1], afh[0], afl[0]);
                hsplit2(Sv[2 * t][2], Sv[2 * t][3], afh[1], afl[1]);
                hsplit2(Sv[2 * t + 1][0], Sv[2 * t + 1][1], afh[2], afl[2]);
                hsplit2(Sv[2 * t + 1][2], Sv[2 * t + 1][3], afh[3], afl[3]);
#pragma unroll
                for (int n2 = 0; n2 < 4; n2++) {
                    uint32_t off = ((n2 * 16 + brow) * VTS + half * 64 + t * 16 + bcol) * 2;
                    uint32_t vh4[4];
                    ldsm4(vh4, sb + OFF_VH + off);
                    mma_f16(O[2 * n2], afh, vh4[0], vh4[1]);
                    mma_f16(O[2 * n2], afl, vh4[0], vh4[1]);
                    mma_f16(O[2 * n2 + 1], afh, vh4[2], vh4[3]);
                    mma_f16(O[2 * n2 + 1], afl, vh4[2], vh4[3]);
                }
            }
        }
    }

    sum0 += __shfl_xor_sync(0xffffffffu, sum0, 1);
    sum0 += __shfl_xor_sync(0xffffffffu, sum0, 2);
    sum1 += __shfl_xor_sync(0xffffffffu, sum1, 1);
    sum1 += __shfl_xor_sync(0xffffffffu, sum1, 2);
    const float inv0 = 1.f / sum0;
    const float inv1 = 1.f / sum1;
    if ((lane & 3) == 0) {
        g_rowl[hb * L_SEQ + ir0] = sum0;
        g_rowl[hb * L_SEQ + ir1] = sum1;
    }

    // epilogue: attnout fp16 hi/lo  [l b][h dv]
    const int h = hb >> 1, bb = hb & 1;
#pragma unroll
    for (int n = 0; n < 8; n++) {
        int dv = n * 8 + jco;
        float x0 = O[n][0] * inv0, x1 = O[n][1] * inv0;
        float y0 = O[n][2] * inv1, y1 = O[n][3] * inv1;
        uint32_t h0, l0, h1, l1;
        hsplit2(x0, x1, h0, l0);
        hsplit2(y0, y1, h1, l1);
        size_t i0x = ((size_t)ir0 * NB + bb) * DM + h * DHEAD + dv;
        size_t i1x = ((size_t)ir1 * NB + bb) * DM + h * DHEAD + dv;
        *(uint32_t*)(g_aohi + i0x) = h0;
        *(uint32_t*)(g_aolo + i0x) = l0;
        *(uint32_t*)(g_aohi + i1x) = h1;
        *(uint32_t*)(g_aolo + i1x) = l1;
    }
}

// =========================================================================
// Normalize: warp-uniform band test; out-of-band warps store zeros only;
// band warps do vectorized loads + select.
// =========================================================================
__global__ void __launch_bounds__(256)
attn_norm_kernel(float* __restrict__ attn)
{
    const int row = blockIdx.x;
    const int i = row & (L_SEQ - 1);
    float* p = attn + (size_t)row * L_SEQ;
    const int t = threadIdx.x;
    const int j0 = t * 8;
    const int w0 = (t >> 5) * 256;               // warp col range [w0, w0+255]
    const bool wtouch = (w0 <= i + SPAN_W) && (w0 + 255 >= i - SPAN_W);
    if (!wtouch) {
        float4 zz = make_float4(0.f, 0.f, 0.f, 0.f);
        *(float4*)&p[j0] = zz;
        *(float4*)&p[j0 + 4] = zz;
        return;
    }
    const float inv = 1.f / g_rowl[row];
    float4 a = *(const float4*)&p[j0];
    float4 b = *(const float4*)&p[j0 + 4];
    float out[8] = {a.x, a.y, a.z, a.w, b.x, b.y, b.z, b.w};
#pragma unroll
    for (int u = 0; u < 8; u++) {
        int d = i - (j0 + u);
        out[u] = (d >= -SPAN_W && d <= SPAN_W) ? out[u] * inv : 0.f;
    }
    *(float4*)&p[j0]     = make_float4(out[0], out[1], out[2], out[3]);
    *(float4*)&p[j0 + 4] = make_float4(out[4], out[5], out[6], out[7]);
}

// =========================================================================
// Residual + LayerNorm.
// =========================================================================
__global__ void __launch_bounds__(256)
ln_kernel(const float* __restrict__ query, const float* __restrict__ gamma,
          const float* __restrict__ beta, float* __restrict__ y)
{
    __shared__ float red[16];
    const int row = blockIdx.x;
    const int t = threadIdx.x;

    float4 f = *(const float4*)&g_fc[(size_t)row * DM + t * 4];
    float4 q = *(const float4*)&query[(size_t)row * DM + t * 4];
    float v0 = f.x + q.x, v1 = f.y + q.y, v2 = f.z + q.z, v3 = f.w + q.w;

    float s = v0 + v1 + v2 + v3;
    float s2 = v0 * v0 + v1 * v1 + v2 * v2 + v3 * v3;
#pragma unroll
    for (int off = 16; off > 0; off >>= 1) {
        s  += __shfl_xor_sync(0xffffffffu, s, off);
        s2 += __shfl_xor_sync(0xffffffffu, s2, off);
    }
    const int warp = t >> 5, lane = t & 31;
    if (lane == 0) { red[warp] = s; red[warp + 8] = s2; }
    __syncthreads();
    if (t < 32) {
        float a  = (lane < 8) ? red[lane] : 0.f;
        float b2 = (lane < 8) ? red[lane + 8] : 0.f;
#pragma unroll
        for (int off = 4; off > 0; off >>= 1) {
            a  += __shfl_xor_sync(0xffffffffu, a, off);
            b2 += __shfl_xor_sync(0xffffffffu, b2, off);
        }
        if (lane == 0) { red[0] = a; red[1] = b2; }
    }
    __syncthreads();
    const float mean = red[0] * (1.f / DM);
    const float var  = red[1] * (1.f / DM) - mean * mean;
    const float rstd = rsqrtf(var + 1e-5f);

    float4 g  = *(const float4*)&gamma[t * 4];
    float4 be = *(const float4*)&beta[t * 4];
    float4 o;
    o.x = (v0 - mean) * rstd * g.x + be.x;
    o.y = (v1 - mean) * rstd * g.y + be.y;
    o.z = (v2 - mean) * rstd * g.z + be.z;
    o.w = (v3 - mean) * rstd * g.w + be.w;
    *(float4*)&y[(size_t)row * DM + t * 4] = o;
}

// =========================================================================
extern "C" void kernel_launch(void* const* d_in, const int* in_sizes, int n_in,
                              void* d_out, int out_size)
{
    const float* query = (const float*)d_in[0];
    const float* key   = (const float*)d_in[1];
    const float* value = (const float*)d_in[2];
    const float* Wq    = (const float*)d_in[3];
    const float* bq    = (const float*)d_in[4];
    const float* Wk    = (const float*)d_in[5];
    const float* bk    = (const float*)d_in[6];
    const float* Wv    = (const float*)d_in[7];
    const float* bv    = (const float*)d_in[8];
    const float* Wfc   = (const float*)d_in[9];
    const float* bfc   = (const float*)d_in[10];
    const float* gamma = (const float*)d_in[11];
    const float* beta  = (const float*)d_in[12];

    float* y_out = (float*)d_out;
    float* attn_out = y_out + (size_t)L_SEQ * NB * DM;

    cudaFuncSetAttribute(attn_kernel,
                         cudaFuncAttributeMaxDynamicSharedMemorySize,
                         ATTN_SMEM_BYTES);
    cudaFuncSetAttribute(mma_gemm_kernel,
                         cudaFuncAttributeMaxDynamicSharedMemorySize,
                         GEMM_SMEM_BYTES);

    conv_w_kernel<<<dim3(DM / 32, DM / 32, 4), 256>>>(Wq, Wk, Wv, Wfc);
    conv_in_kernel<<<dim3(MROWS * DM / 2048, 3), 256>>>(query, key, value);

    mma_gemm_kernel<<<dim3(MROWS / 128, DM / 128, 3), 256, GEMM_SMEM_BYTES>>>(
        bq, bk, bv, bfc, 0);

    attn_kernel<<<dim3(L_SEQ / 128, HB), 256, ATTN_SMEM_BYTES>>>(attn_out);

    mma_gemm_kernel<<<dim3(MROWS / 128, DM / 128, 1), 256, GEMM_SMEM_BYTES>>>(
        bq, bk, bv, bfc, 1);

    ln_kernel<<<MROWS, 256>>>(query, gamma, beta, y_out);

    attn_norm_kernel<<<HB * L_SEQ, 256>>>(attn_out);
}

// round 9
// speedup vs baseline: 3.6307x; 1.0713x over previous
#include <cuda_runtime.h>
#include <cuda_fp16.h>
#include <math.h>
#include <float.h>
#include <stdint.h>

#define L_SEQ 2048
#define NB 2
#define DM 1024
#define NH 16
#define DHEAD 64
#define SPAN_W 128
#define MROWS (L_SEQ * NB)          // 4096
#define HB (NH * NB)                // 32

// ---------------- static scratch (no allocations allowed) ----------------
__device__ float g_fc[MROWS * DM];               // FC output (pre-LN)
__device__ float g_rowl[HB * L_SEQ];             // softmax row sum

// fp16 operands
__device__ __half g_inhi[3][MROWS * DM];         // q/k/v inputs hi
__device__ __half g_inlo[3][MROWS * DM];         // lo (z<2 only used)
__device__ __half g_wth[4][DM * DM];             // W^T [n][k] (single fp16)
__device__ __half g_aohi[MROWS * DM];            // attnout (single fp16)
// projected Q (x0.125) hi/lo + K single, head-major [hb][l][dk]
__device__ __half g_qh[HB * L_SEQ * DHEAD];
__device__ __half g_ql[HB * L_SEQ * DHEAD];
__device__ __half g_kh[HB * L_SEQ * DHEAD];
// projected V transposed [hb][dv][l], single fp16
__device__ __half g_vth[HB * DHEAD * L_SEQ];

// ---------------- helpers ----------------
__device__ __forceinline__ uint32_t smem_u32(const void* p) {
    uint32_t a;
    asm("{ .reg .u64 t; cvta.to.shared.u64 t, %1; cvt.u32.u64 %0, t; }"
        : "=r"(a) : "l"(p));
    return a;
}
__device__ __forceinline__ void ldsm4(uint32_t (&r)[4], uint32_t addr) {
    asm volatile("ldmatrix.sync.aligned.m8n8.x4.shared.b16 {%0,%1,%2,%3}, [%4];"
                 : "=r"(r[0]), "=r"(r[1]), "=r"(r[2]), "=r"(r[3]) : "r"(addr));
}
__device__ __forceinline__ void mma_f16(float (&d)[4], const uint32_t (&a)[4],
                                        uint32_t b0, uint32_t b1) {
    asm volatile(
        "mma.sync.aligned.m16n8k16.row.col.f32.f16.f16.f32 "
        "{%0,%1,%2,%3}, {%4,%5,%6,%7}, {%8,%9}, {%0,%1,%2,%3};"
        : "+f"(d[0]), "+f"(d[1]), "+f"(d[2]), "+f"(d[3])
        : "r"(a[0]), "r"(a[1]), "r"(a[2]), "r"(a[3]), "r"(b0), "r"(b1));
}
#define CPA16(saddr, gptr) \
    asm volatile("cp.async.cg.shared.global [%0], [%1], 16;" \
                 :: "r"(saddr), "l"(__cvta_generic_to_global(gptr)) : "memory")
#define CPA_COMMIT() asm volatile("cp.async.commit_group;" ::: "memory")
#define CPA_WAIT0()  asm volatile("cp.async.wait_group 0;" ::: "memory")

// fast exp on FMA pipe, ~1e-7 rel (|x| < 80)
__device__ __forceinline__ float fexp(float x) {
    x = fmaxf(x, -80.f);
    float t = fmaf(x, 1.4426950408889634f, 12582912.f);
    float n = t - 12582912.f;
    float f = fmaf(n, -0.693145751953125f, x);
    f = fmaf(n, -1.428606765330187e-06f, f);
    float p = 1.3888889e-3f;
    p = fmaf(p, f, 8.3333338e-3f);
    p = fmaf(p, f, 4.1666668e-2f);
    p = fmaf(p, f, 1.6666667e-1f);
    p = fmaf(p, f, 5.0e-1f);
    p = fmaf(p, f, 1.0f);
    p = fmaf(p, f, 1.0f);
    int i = (int)n;
    return __int_as_float(__float_as_int(p) + (i << 23));
}
__device__ __forceinline__ uint32_t packh2(float a, float b) {
    __half2 t = __floats2half2_rn(a, b);
    return *reinterpret_cast<uint32_t*>(&t);
}
__device__ __forceinline__ void hsplit2(float a, float b, uint32_t& h, uint32_t& l) {
    __half ha = __float2half_rn(a), hb = __float2half_rn(b);
    __half2 hh = __halves2half2(ha, hb);
    h = *reinterpret_cast<uint32_t*>(&hh);
    l = packh2(a - __half2float(ha), b - __half2float(hb));
}

// ======================== converter kernels ==============================
__global__ void __launch_bounds__(256)
conv_in_kernel(const float* __restrict__ q, const float* __restrict__ k,
               const float* __restrict__ v)
{
    const int z = blockIdx.y;
    const float* src = (z == 0) ? q : (z == 1) ? k : v;
    __half* dhi = g_inhi[z];
    __half* dlo = g_inlo[z];
    size_t base = ((size_t)blockIdx.x * 256 + threadIdx.x) * 8;
    float4 a = *(const float4*)(src + base);
    float4 b = *(const float4*)(src + base + 4);
    __half hi[8], lo[8];
    float xs[8] = {a.x, a.y, a.z, a.w, b.x, b.y, b.z, b.w};
#pragma unroll
    for (int i = 0; i < 8; i++) {
        hi[i] = __float2half_rn(xs[i]);
        lo[i] = __float2half_rn(xs[i] - __half2float(hi[i]));
    }
    *(uint4*)(dhi + base) = *(uint4*)hi;
    if (z < 2) *(uint4*)(dlo + base) = *(uint4*)lo;   // V projection is 1-term
}

__global__ void __launch_bounds__(256)
conv_w_kernel(const float* __restrict__ Wq, const float* __restrict__ Wk,
              const float* __restrict__ Wv, const float* __restrict__ Wfc)
{
    __shared__ float tile[32][33];
    const int z = blockIdx.z;
    const float* W = (z == 0) ? Wq : (z == 1) ? Wk : (z == 2) ? Wv : Wfc;
    __half* dh = g_wth[z];
    const int n0 = blockIdx.x * 32, k0 = blockIdx.y * 32;
    const int c = threadIdx.x & 31, r0 = (threadIdx.x >> 5) * 4;
#pragma unroll
    for (int rr = 0; rr < 4; rr++)
        tile[r0 + rr][c] = W[(size_t)(k0 + r0 + rr) * DM + n0 + c];
    __syncthreads();
#pragma unroll
    for (int rr = 0; rr < 4; rr++) {
        int n = n0 + r0 + rr;
        dh[(size_t)n * DM + k0 + c] = __float2half_rn(tile[c][r0 + rr]);
    }
}

// ======================== fp16 HMMA GEMM (cp.async) ======================
// Q/K proj: D = (Ah + Al) @ Bh (2-term).  V proj / FC: D = Ah @ Bh (1-term).
#define TSX 40
#define TILE_B (128 * TSX * 2)
#define GEMM_SMEM_BYTES (2 * 3 * TILE_B)   // 61440

__global__ void __launch_bounds__(256, 2)
mma_gemm_kernel(const float* __restrict__ bq, const float* __restrict__ bk,
                const float* __restrict__ bv, const float* __restrict__ bfc,
                int is_fc)
{
    extern __shared__ char dyn[];
    const uint32_t sb = smem_u32(dyn);
    const int tid = threadIdx.x, wid = tid >> 5, lane = tid & 31;
    const int m0 = blockIdx.x * 128, n0 = blockIdx.y * 128;
    const int z = blockIdx.z;
    const int use_lo = is_fc ? 0 : (z < 2);

    const __half *Ah, *Al, *Bh;
    const float* bias;
    if (is_fc) {
        Ah = g_aohi; Al = g_aohi; Bh = g_wth[3]; bias = bfc;
    } else {
        Ah = g_inhi[z]; Al = g_inlo[z]; Bh = g_wth[z];
        bias = (z == 0) ? bq : (z == 1) ? bk : bv;
    }
    const __half* srcs[3] = {
        Ah + (size_t)m0 * DM, Al + (size_t)m0 * DM, Bh + (size_t)n0 * DM };

    const int wm = (wid & 3) * 32;
    const int wn = (wid >> 2) * 64;

    float acc[2][8][4];
#pragma unroll
    for (int ms = 0; ms < 2; ms++)
#pragma unroll
        for (int ns = 0; ns < 8; ns++)
#pragma unroll
            for (int c = 0; c < 4; c++) acc[ms][ns][c] = 0.f;

    const int r_ld = tid >> 2;
    const int c_ld = (tid & 3) * 8;

    auto issue_tile = [&](int buf, int k0) {
#pragma unroll
        for (int t = 0; t < 3; t++) {
            if (t == 1 && !use_lo) continue;
#pragma unroll
            for (int u = 0; u < 2; u++) {
                uint32_t sa = sb + buf * (3 * TILE_B) + t * TILE_B +
                              ((r_ld + u * 64) * TSX + c_ld) * 2;
                CPA16(sa, srcs[t] + (size_t)(r_ld + u * 64) * DM + k0 + c_ld);
            }
        }
        CPA_COMMIT();
    };

    issue_tile(0, 0);
    CPA_WAIT0();
    __syncthreads();

    const int rowA = wm + (lane & 15);
    const int colA = (lane >> 4) << 3;
    const int rowB = wn + (lane & 7) + ((lane >> 4) << 3);
    const int colB = ((lane >> 3) & 1) << 3;

    for (int step = 0; step < 32; step++) {
        const int buf = step & 1;
        const uint32_t base = sb + buf * (3 * TILE_B);
        const int has_next = (step + 1 < 32);
        if (has_next) issue_tile(buf ^ 1, (step + 1) * 32);

#pragma unroll
        for (int kh = 0; kh < 32; kh += 16) {
            uint32_t ah[2][4], al[2][4];
#pragma unroll
            for (int ms = 0; ms < 2; ms++) {
                uint32_t off = ((rowA + ms * 16) * TSX + kh + colA) * 2;
                ldsm4(ah[ms], base + 0 * TILE_B + off);
                if (use_lo) ldsm4(al[ms], base + 1 * TILE_B + off);
            }
            uint32_t bh[8][2];
#pragma unroll
            for (int np = 0; np < 4; np++) {
                uint32_t off = ((rowB + np * 16) * TSX + kh + colB) * 2;
                uint32_t t4[4];
                ldsm4(t4, base + 2 * TILE_B + off);
                bh[2 * np][0] = t4[0]; bh[2 * np][1] = t4[1];
                bh[2 * np + 1][0] = t4[2]; bh[2 * np + 1][1] = t4[3];
            }
#pragma unroll
            for (int ms = 0; ms < 2; ms++)
#pragma unroll
                for (int ns = 0; ns < 8; ns++) {
                    mma_f16(acc[ms][ns], ah[ms], bh[ns][0], bh[ns][1]);
                    if (use_lo) mma_f16(acc[ms][ns], al[ms], bh[ns][0], bh[ns][1]);
                }
        }
        if (has_next) {
            CPA_WAIT0();
            __syncthreads();
        }
    }

    const int qrow = lane >> 2;
    const int qcol = (lane & 3) * 2;
    const float scale = (!is_fc && z == 0) ? 0.125f : 1.0f;
#pragma unroll
    for (int ms = 0; ms < 2; ms++) {
#pragma unroll
        for (int ns = 0; ns < 8; ns++) {
            const int ncol = n0 + wn + ns * 8 + qcol;
            const float b0 = bias[ncol], b1 = bias[ncol + 1];
#pragma unroll
            for (int half = 0; half < 2; half++) {
                const int m = m0 + wm + ms * 16 + qrow + half * 8;
                float x0 = (acc[ms][ns][2 * half] + b0) * scale;
                float x1 = (acc[ms][ns][2 * half + 1] + b1) * scale;
                if (is_fc) {
                    *(float2*)(g_fc + (size_t)m * DM + ncol) = make_float2(x0, x1);
                } else {
                    const int l = m >> 1, bb = m & 1;
                    const int h = ncol >> 6, dkb = ncol & 63;
                    if (z == 0) {
                        size_t idx = ((size_t)(h * NB + bb) * L_SEQ + l) * DHEAD + dkb;
                        uint32_t ph, pl;
                        hsplit2(x0, x1, ph, pl);
                        *(uint32_t*)(g_qh + idx) = ph;
                        *(uint32_t*)(g_ql + idx) = pl;
                    } else if (z == 1) {
                        size_t idx = ((size_t)(h * NB + bb) * L_SEQ + l) * DHEAD + dkb;
                        *(uint32_t*)(g_kh + idx) = packh2(x0, x1);
                    } else {
                        size_t base2 = ((size_t)(h * NB + bb) * DHEAD + dkb) * L_SEQ + l;
                        g_vth[base2] = __float2half_rn(x0);
                        g_vth[base2 + L_SEQ] = __float2half_rn(x1);
                    }
                }
            }
        }
    }
}

// =========================================================================
// fp16 HMMA banded attention, single pass, P in registers.
// S = (Qh+Ql) Kh^T (2-term) ;  O = Ph Vh (1-term).
// =========================================================================
#define QKS 72           // Q/K smem row stride (halves)
#define VTS 136          // Vt smem row stride
#define OFF_QH 0
#define OFF_QL 18432
#define OFF_KH 36864
#define OFF_VH 55296
#define ATTN_SMEM_BYTES (55296 + 64 * VTS * 2)   // 72704

__global__ void __launch_bounds__(256, 2)
attn_kernel(float* __restrict__ attn_raw)
{
    extern __shared__ char dyn[];
    const uint32_t sb = smem_u32(dyn);
    const int tid = threadIdx.x, wid = tid >> 5, lane = tid & 31;
    const int w16 = wid * 16;
    const int i0 = blockIdx.x * 128;
    const int hb = blockIdx.y;

    const __half* Qh = g_qh + (size_t)hb * L_SEQ * DHEAD;
    const __half* Ql = g_ql + (size_t)hb * L_SEQ * DHEAD;
    const __half* Kh = g_kh + (size_t)hb * L_SEQ * DHEAD;
    const __half* Vh = g_vth + (size_t)hb * DHEAD * L_SEQ;
    float* rawbase = attn_raw + (size_t)hb * L_SEQ * L_SEQ;

    // load Q tile (persistent)
    {
        const __half* src = Qh + (size_t)i0 * DHEAD;
        const __half* srl = Ql + (size_t)i0 * DHEAD;
#pragma unroll
        for (int u = 0; u < 4; u++) {
            int idx = tid + u * 256;
            int r = idx >> 3, c = idx & 7;
            *(uint4*)(dyn + OFF_QH + (r * QKS + c * 8) * 2) =
                *(const uint4*)(src + (size_t)r * DHEAD + c * 8);
            *(uint4*)(dyn + OFF_QL + (r * QKS + c * 8) * 2) =
                *(const uint4*)(srl + (size_t)r * DHEAD + c * 8);
        }
    }

    const int ir0 = i0 + w16 + (lane >> 2);
    const int ir1 = ir0 + 8;
    const int jco = 2 * (lane & 3);

    const uint32_t qoff = ((w16 + (lane & 15)) * QKS + ((lane >> 4) << 3)) * 2;
    const uint32_t brow = (lane & 7) + ((lane >> 4) << 3);
    const uint32_t bcol = ((lane >> 3) & 1) << 3;

    float O[8][4];
#pragma unroll
    for (int n = 0; n < 8; n++)
#pragma unroll
        for (int e = 0; e < 4; e++) O[n][e] = 0.f;
    float sum0 = 0.f, sum1 = 0.f;

    for (int cch = 0; cch < 3; cch++) {
        int j0 = i0 + (cch - 1) * 128;
        if (j0 < 0 || j0 >= L_SEQ) continue;
        __syncthreads();     // prev chunk K/V fully consumed
        {
#pragma unroll
            for (int u = 0; u < 4; u++) {
                int idx = tid + u * 256;
                int r = idx >> 3, c = idx & 7;
                *(uint4*)(dyn + OFF_KH + (r * QKS + c * 8) * 2) =
                    *(const uint4*)(Kh + (size_t)(j0 + r) * DHEAD + c * 8);
            }
#pragma unroll
            for (int u = 0; u < 4; u++) {
                int idx = tid + u * 256;
                int r = idx >> 4, c = idx & 15;
                *(uint4*)(dyn + OFF_VH + (r * VTS + c * 8) * 2) =
                    *(const uint4*)(Vh + (size_t)r * L_SEQ + j0 + c * 8);
            }
        }
        __syncthreads();

#pragma unroll
        for (int half = 0; half < 2; half++) {
            // ---- S = Q K^T for 64 j-cols ----
            float Sv[8][4];
#pragma unroll
            for (int n = 0; n < 8; n++)
#pragma unroll
                for (int e = 0; e < 4; e++) Sv[n][e] = 0.f;
#pragma unroll
            for (int ks = 0; ks < 4; ks++) {
                uint32_t ah[4], al[4];
                ldsm4(ah, sb + OFF_QH + qoff + ks * 32);
                ldsm4(al, sb + OFF_QL + qoff + ks * 32);
#pragma unroll
                for (int n2 = 0; n2 < 4; n2++) {
                    uint32_t off = ((half * 64 + n2 * 16 + brow) * QKS + ks * 16 + bcol) * 2;
                    uint32_t kh4[4];
                    ldsm4(kh4, sb + OFF_KH + off);
                    mma_f16(Sv[2 * n2], ah, kh4[0], kh4[1]);
                    mma_f16(Sv[2 * n2], al, kh4[0], kh4[1]);
                    mma_f16(Sv[2 * n2 + 1], ah, kh4[2], kh4[3]);
                    mma_f16(Sv[2 * n2 + 1], al, kh4[2], kh4[3]);
                }
            }

            // ---- mask + exp (m=0) + gmem p + row sums ----
#pragma unroll
            for (int n = 0; n < 8; n++) {
                int j = j0 + half * 64 + n * 8 + jco;
                int d0 = ir0 - j, d1 = ir1 - j;
                float p00 = (d0 >= -SPAN_W && d0 <= SPAN_W) ? fexp(Sv[n][0]) : 0.f;
                float p01 = (d0 - 1 >= -SPAN_W && d0 - 1 <= SPAN_W) ? fexp(Sv[n][1]) : 0.f;
                float p10 = (d1 >= -SPAN_W && d1 <= SPAN_W) ? fexp(Sv[n][2]) : 0.f;
                float p11 = (d1 - 1 >= -SPAN_W && d1 - 1 <= SPAN_W) ? fexp(Sv[n][3]) : 0.f;
                sum0 += p00 + p01;
                sum1 += p10 + p11;
                *(float2*)(rawbase + (size_t)ir0 * L_SEQ + j) = make_float2(p00, p01);
                *(float2*)(rawbase + (size_t)ir1 * L_SEQ + j) = make_float2(p10, p11);
                Sv[n][0] = p00; Sv[n][1] = p01; Sv[n][2] = p10; Sv[n][3] = p11;
            }

            // ---- O += P V (single-term P, A-fragments from registers) ----
#pragma unroll
            for (int t = 0; t < 4; t++) {
                uint32_t af[4];
                af[0] = packh2(Sv[2 * t][0], Sv[2 * t][1]);
                af[1] = packh2(Sv[2 * t][2], Sv[2 * t][3]);
                af[2] = packh2(Sv[2 * t + 1][0], Sv[2 * t + 1][1]);
                af[3] = packh2(Sv[2 * t + 1][2], Sv[2 * t + 1][3]);
#pragma unroll
                for (int n2 = 0; n2 < 4; n2++) {
                    uint32_t off = ((n2 * 16 + brow) * VTS + half * 64 + t * 16 + bcol) * 2;
                    uint32_t vh4[4];
                    ldsm4(vh4, sb + OFF_VH + off);
                    mma_f16(O[2 * n2], af, vh4[0], vh4[1]);
                    mma_f16(O[2 * n2 + 1], af, vh4[2], vh4[3]);
                }
            }
        }
    }

    sum0 += __shfl_xor_sync(0xffffffffu, sum0, 1);
    sum0 += __shfl_xor_sync(0xffffffffu, sum0, 2);
    sum1 += __shfl_xor_sync(0xffffffffu, sum1, 1);
    sum1 += __shfl_xor_sync(0xffffffffu, sum1, 2);
    const float inv0 = 1.f / sum0;
    const float inv1 = 1.f / sum1;
    if ((lane & 3) == 0) {
        g_rowl[hb * L_SEQ + ir0] = sum0;
        g_rowl[hb * L_SEQ + ir1] = sum1;
    }

    // epilogue: attnout single fp16  [l b][h dv]
    const int h = hb >> 1, bb = hb & 1;
#pragma unroll
    for (int n = 0; n < 8; n++) {
        int dv = n * 8 + jco;
        size_t i0x = ((size_t)ir0 * NB + bb) * DM + h * DHEAD + dv;
        size_t i1x = ((size_t)ir1 * NB + bb) * DM + h * DHEAD + dv;
        *(uint32_t*)(g_aohi + i0x) = packh2(O[n][0] * inv0, O[n][1] * inv0);
        *(uint32_t*)(g_aohi + i1x) = packh2(O[n][2] * inv1, O[n][3] * inv1);
    }
}

// =========================================================================
// Normalize: per-8-group band test; only overlapping groups load.
// =========================================================================
__global__ void __launch_bounds__(256)
attn_norm_kernel(float* __restrict__ attn)
{
    const int row = blockIdx.x;
    const int i = row & (L_SEQ - 1);
    float* p = attn + (size_t)row * L_SEQ;
    const int j0 = threadIdx.x * 8;
    const bool overlap = (j0 + 7 >= i - SPAN_W) && (j0 <= i + SPAN_W);
    if (!overlap) {
        float4 zz = make_float4(0.f, 0.f, 0.f, 0.f);
        *(float4*)&p[j0] = zz;
        *(float4*)&p[j0 + 4] = zz;
        return;
    }
    const float inv = 1.f / g_rowl[row];
    float4 a = *(const float4*)&p[j0];
    float4 b = *(const float4*)&p[j0 + 4];
    float out[8] = {a.x, a.y, a.z, a.w, b.x, b.y, b.z, b.w};
#pragma unroll
    for (int u = 0; u < 8; u++) {
        int d = i - (j0 + u);
        out[u] = (d >= -SPAN_W && d <= SPAN_W) ? out[u] * inv : 0.f;
    }
    *(float4*)&p[j0]     = make_float4(out[0], out[1], out[2], out[3]);
    *(float4*)&p[j0 + 4] = make_float4(out[4], out[5], out[6], out[7]);
}

// =========================================================================
// Residual + LayerNorm.
// =========================================================================
__global__ void __launch_bounds__(256)
ln_kernel(const float* __restrict__ query, const float* __restrict__ gamma,
          const float* __restrict__ beta, float* __restrict__ y)
{
    __shared__ float red[16];
    const int row = blockIdx.x;
    const int t = threadIdx.x;

    float4 f = *(const float4*)&g_fc[(size_t)row * DM + t * 4];
    float4 q = *(const float4*)&query[(size_t)row * DM + t * 4];
    float v0 = f.x + q.x, v1 = f.y + q.y, v2 = f.z + q.z, v3 = f.w + q.w;

    float s = v0 + v1 + v2 + v3;
    float s2 = v0 * v0 + v1 * v1 + v2 * v2 + v3 * v3;
#pragma unroll
    for (int off = 16; off > 0; off >>= 1) {
        s  += __shfl_xor_sync(0xffffffffu, s, off);
        s2 += __shfl_xor_sync(0xffffffffu, s2, off);
    }
    const int warp = t >> 5, lane = t & 31;
    if (lane == 0) { red[warp] = s; red[warp + 8] = s2; }
    __syncthreads();
    if (t < 32) {
        float a  = (lane < 8) ? red[lane] : 0.f;
        float b2 = (lane < 8) ? red[lane + 8] : 0.f;
#pragma unroll
        for (int off = 4; off > 0; off >>= 1) {
            a  += __shfl_xor_sync(0xffffffffu, a, off);
            b2 += __shfl_xor_sync(0xffffffffu, b2, off);
        }
        if (lane == 0) { red[0] = a; red[1] = b2; }
    }
    __syncthreads();
    const float mean = red[0] * (1.f / DM);
    const float var  = red[1] * (1.f / DM) - mean * mean;
    const float rstd = rsqrtf(var + 1e-5f);

    float4 g  = *(const float4*)&gamma[t * 4];
    float4 be = *(const float4*)&beta[t * 4];
    float4 o;
    o.x = (v0 - mean) * rstd * g.x + be.x;
    o.y = (v1 - mean) * rstd * g.y + be.y;
    o.z = (v2 - mean) * rstd * g.z + be.z;
    o.w = (v3 - mean) * rstd * g.w + be.w;
    *(float4*)&y[(size_t)row * DM + t * 4] = o;
}

// =========================================================================
extern "C" void kernel_launch(void* const* d_in, const int* in_sizes, int n_in,
                              void* d_out, int out_size)
{
    const float* query = (const float*)d_in[0];
    const float* key   = (const float*)d_in[1];
    const float* value = (const float*)d_in[2];
    const float* Wq    = (const float*)d_in[3];
    const float* bq    = (const float*)d_in[4];
    const float* Wk    = (const float*)d_in[5];
    const float* bk    = (const float*)d_in[6];
    const float* Wv    = (const float*)d_in[7];
    const float* bv    = (const float*)d_in[8];
    const float* Wfc   = (const float*)d_in[9];
    const float* bfc   = (const float*)d_in[10];
    const float* gamma = (const float*)d_in[11];
    const float* beta  = (const float*)d_in[12];

    float* y_out = (float*)d_out;
    float* attn_out = y_out + (size_t)L_SEQ * NB * DM;

    cudaFuncSetAttribute(attn_kernel,
                         cudaFuncAttributeMaxDynamicSharedMemorySize,
                         ATTN_SMEM_BYTES);
    cudaFuncSetAttribute(mma_gemm_kernel,
                         cudaFuncAttributeMaxDynamicSharedMemorySize,
                         GEMM_SMEM_BYTES);

    conv_w_kernel<<<dim3(DM / 32, DM / 32, 4), 256>>>(Wq, Wk, Wv, Wfc);
    conv_in_kernel<<<dim3(MROWS * DM / 2048, 3), 256>>>(query, key, value);

    mma_gemm_kernel<<<dim3(MROWS / 128, DM / 128, 3), 256, GEMM_SMEM_BYTES>>>(
        bq, bk, bv, bfc, 0);

    attn_kernel<<<dim3(L_SEQ / 128, HB), 256, ATTN_SMEM_BYTES>>>(attn_out);

    mma_gemm_kernel<<<dim3(MROWS / 128, DM / 128, 1), 256, GEMM_SMEM_BYTES>>>(
        bq, bk, bv, bfc, 1);

    ln_kernel<<<MROWS, 256>>>(query, gamma, beta, y_out);

    attn_norm_kernel<<<HB * L_SEQ, 256>>>(attn_out);
}